// round 8
// baseline (speedup 1.0000x reference)
#include <cuda_runtime.h>
#include <cuda_bf16.h>
#include <math.h>

// Problem constants
#define B 64
#define NA 33600            // 160*160 + 80*80 + 40*40
#define NA4 8400            // NA / 4
#define TOPK 500
#define CAND 1024           // candidate sort size
#define NBIN 1024           // linear histogram bins over (0.3, 1.0]
#define SCORE_THRESH 0.3f
#define NMS_THRESH 0.5f
#define CLASS_OFFSET 10000.0f

#define P3_END 25600
#define P4_END 32000

typedef unsigned long long ull;

// ---------------- scratch (static device allocations; no runtime alloc) ----
__device__ float g_scores[B * NA];      // used ONLY by the pathological fallback
__device__ ull   g_cand[B * NA];        // per-batch approx candidate keys
__device__ int   g_cnt[B];              // per-batch candidate counts
__device__ int   g_hist[B][NBIN];       // per-batch approx-score histograms

// ------------------------------------------------------------ exp/sigmoid --
// Correctly-rounded float exp via double exp (matches XLA:CPU expf).
// Verified bit-compatible in R4-R7 — DO NOT change.
__device__ __forceinline__ float exp_cr(float x) {
    return (float)exp((double)x);
}
__device__ __forceinline__ float sig_e(float x) {
    float e = exp_cr(-x);
    return __fdiv_rn(1.0f, __fadd_rn(1.0f, e));
}
// fast sigmoid for the approximate path (product abs err < ~3e-6)
__device__ __forceinline__ float sig_fast(float x) {
    return __fdividef(1.0f, 1.0f + __expf(-x));
}

__device__ __forceinline__ unsigned int ordered_float(float f) {
    unsigned int u = __float_as_uint(f);
    return (u & 0x80000000u) ? ~u : (u | 0x80000000u);
}
__device__ __forceinline__ float inv_ordered(unsigned int u) {
    return __uint_as_float((u & 0x80000000u) ? (u ^ 0x80000000u) : ~u);
}
// monotone linear bin over (0.3, 1.0]
__device__ __forceinline__ int bin_of(float s) {
    int q = (int)(__fmul_rn(__fsub_rn(s, 0.3f), 1462.857f));
    if (q < 0) q = 0;
    return (q > NBIN - 1) ? (NBIN - 1) : q;
}

__device__ __forceinline__ void level_of(int idx, int& HW, int& W, float& stride, int& p, int& lvl) {
    if (idx < P3_END)      { HW = 25600; W = 160; stride = 8.f;  p = idx;          lvl = 0; }
    else if (idx < P4_END) { HW = 6400;  W = 80;  stride = 16.f; p = idx - P3_END; lvl = 1; }
    else                   { HW = 1600;  W = 40;  stride = 32.f; p = idx - P4_END; lvl = 2; }
}

// ------------------------------------------- decode (pure float approx) ----
__global__ void decode_approx_kernel(const float* __restrict__ cls3,
                                     const float* __restrict__ obj3,
                                     const float* __restrict__ cls4,
                                     const float* __restrict__ obj4,
                                     const float* __restrict__ cls5,
                                     const float* __restrict__ obj5)
{
    int b = blockIdx.y;
    int q = blockIdx.x * 256 + threadIdx.x;
    if (q >= NA4) return;
    int a = q * 4;

    const float* cls; const float* obj; int HW, p;
    if (a < P3_END)      { cls = cls3; obj = obj3; HW = 25600; p = a; }
    else if (a < P4_END) { cls = cls4; obj = obj4; HW = 6400;  p = a - P3_END; }
    else                 { cls = cls5; obj = obj5; HW = 1600;  p = a - P4_END; }

    float4 o4  = *(const float4*)(obj + b * HW + p);
    float4 c04 = *(const float4*)(cls + (b * 2 + 0) * HW + p);
    float4 c14 = *(const float4*)(cls + (b * 2 + 1) * HW + p);

    float oo[4]  = {o4.x, o4.y, o4.z, o4.w};
    float cc0[4] = {c04.x, c04.y, c04.z, c04.w};
    float cc1[4] = {c14.x, c14.y, c14.z, c14.w};

    float ap[4]; bool ps[4]; int cnt = 0;
    #pragma unroll
    for (int j = 0; j < 4; ++j) {
        float cm = fmaxf(cc0[j], cc1[j]);
        float v  = sig_fast(oo[j]) * sig_fast(cm);
        ap[j] = v;
        ps[j] = (v >= 0.29999f);     // exact>0.3 ⇒ approx ≥ 0.299997 ≥ this
        cnt  += ps[j] ? 1 : 0;
    }
    if (cnt) {
        int pos = atomicAdd(&g_cnt[b], cnt);
        ull* dst = g_cand + b * NA;
        #pragma unroll
        for (int j = 0; j < 4; ++j) {
            if (ps[j]) {
                int ai = a + j;
                dst[pos++] = ((ull)ordered_float(ap[j]) << 32) |
                             (unsigned int)(~(unsigned int)ai);
                atomicAdd(&g_hist[b][bin_of(ap[j])], 1);
            }
        }
    }
}

// ------------------------------- fused select (exact top-k) + NMS ----------
__global__ void select_nms_kernel(const float* __restrict__ cls3,
                                  const float* __restrict__ reg3,
                                  const float* __restrict__ obj3,
                                  const float* __restrict__ cls4,
                                  const float* __restrict__ reg4,
                                  const float* __restrict__ obj4,
                                  const float* __restrict__ cls5,
                                  const float* __restrict__ reg5,
                                  const float* __restrict__ obj5,
                                  float* __restrict__ out)
{
    // shared memory union: select phase (16KB) vs NMS phase (42KB)
    __shared__ __align__(16) unsigned char smem_raw[43008];
    int*    hist = (int*)smem_raw;                    // [0, 4K)   select + radix
    int*    cidx = (int*)(smem_raw + 4096);           // [4K, 8K)  gathered anchor idx
    ull*    ckey = (ull*)(smem_raw + 8192);           // [8K, 16K) exact keys / sort
    float4* sbox = (float4*)smem_raw;                 // [0, 8K)   NMS phase
    float*  sar  = (float*)(smem_raw + 8192);         // [8K, 10K)
    unsigned int* adj = (unsigned int*)(smem_raw + 10240); // [10K, 42K) 512x16

    __shared__ int  coarse[NBIN / 4];
    __shared__ int  s_qp, s_cnt, s_nvalid, s_fallback;
    __shared__ ull  s_prefix;
    __shared__ int  s_k;
    __shared__ unsigned int s_validw[16];
    __shared__ unsigned char skeep[512];
    __shared__ unsigned int s_vbm[32];     // valid bitmap over anchor idx [0,1024)
    __shared__ int  s_wpre[33];            // invalid-count prefix over bitmap words

    int b   = blockIdx.x;
    int tid = threadIdx.x;
    int cnt_all = g_cnt[b];

    const float* CLS[3] = {cls3, cls4, cls5};
    const float* REG[3] = {reg3, reg4, reg5};
    const float* OBJ[3] = {obj3, obj4, obj5};

    if (tid == 0) { s_cnt = 0; s_nvalid = 0; s_fallback = 0; }
    if (tid < 32) s_vbm[tid] = 0u;
    __syncthreads();

    const ull* cl = g_cand + b * NA;

    if (cnt_all <= CAND) {
        // ---- small path: take ALL candidates directly ----
        for (int i = tid; i < cnt_all; i += 512)
            cidx[i] = (int)(~(unsigned int)cl[i]);
        if (tid == 0) s_cnt = cnt_all;
        __syncthreads();
    } else {
        // ---- histogram path: pivot bin, then gather bins >= qp-1 ----
        for (int d = tid; d < NBIN; d += 512) hist[d] = g_hist[b][d];
        __syncthreads();
        if (tid < NBIN / 4)
            coarse[tid] = hist[4 * tid] + hist[4 * tid + 1] + hist[4 * tid + 2] + hist[4 * tid + 3];
        __syncthreads();
        if (tid == 0) {
            int cum = 0, qp = 0;
            for (int g = NBIN / 4 - 1; g >= 0; --g) {
                if (cum + coarse[g] >= TOPK) {
                    for (int d = 4 * g + 3; d >= 4 * g; --d) {
                        if (cum + hist[d] >= TOPK) { qp = d; break; }
                        cum += hist[d];
                    }
                    break;
                }
                cum += coarse[g];
            }
            s_qp = (qp > 0) ? qp - 1 : 0;   // 1-bin relaxation covers approx error
        }
        __syncthreads();
        int qp = s_qp;
        for (int i = tid; i < cnt_all; i += 512) {
            ull key = cl[i];
            float s = inv_ordered((unsigned int)(key >> 32));
            if (bin_of(s) >= qp) {
                int pos = atomicAdd(&s_cnt, 1);
                if (pos < CAND) cidx[pos] = (int)(~(unsigned int)key);
                else            s_fallback = 1;   // pathological: too many ties
            }
        }
        __syncthreads();
    }

    // ---- exact scores for the gathered candidates ----
    if (!s_fallback) {
        int m = s_cnt;
        for (int it = tid; it < m; it += 512) {
            int idx = cidx[it];
            int HW, W, p, lvl; float stride;
            level_of(idx, HW, W, stride, p, lvl);
            const float* cls = CLS[lvl];
            const float* obj = OBJ[lvl];
            float o  = obj[b * HW + p];
            float c0 = cls[(b * 2 + 0) * HW + p];
            float c1 = cls[(b * 2 + 1) * HW + p];
            float cmax = fmaxf(c0, c1);
            float so   = sig_e(o);
            float scm  = sig_e(cmax);
            float smax = __fmul_rn(so, scm);     // == max(s0,s1), monotonicity
            ull key = 0ull;
            if (smax > SCORE_THRESH) {
                key = ((ull)ordered_float(smax) << 32) |
                      (unsigned int)(~(unsigned int)idx);
                atomicAdd(&s_nvalid, 1);
                if ((unsigned int)idx < 1024u)
                    atomicOr(&s_vbm[idx >> 5], 1u << (idx & 31));
            }
            ckey[it] = key;
        }
        __syncthreads();

        if (s_nvalid < TOPK) {
            if (cnt_all <= CAND) {
                // ---- cheap pad path: fill with smallest invalid anchor indices
                // (all valid anchors are in ckey, so bitmap is complete for [0,1024))
                if (tid == 0) {
                    int acc = 0;
                    for (int w = 0; w < 32; ++w) {
                        s_wpre[w] = acc;
                        acc += 32 - __popc(s_vbm[w]);
                    }
                    s_wpre[32] = acc;
                }
                __syncthreads();
                int M = TOPK - s_nvalid;       // pads needed (<= 500; always available)
                int base = s_cnt;
                #pragma unroll
                for (int q2 = 0; q2 < 2; ++q2) {
                    int i = tid + q2 * 512;
                    unsigned int bmw = s_vbm[i >> 5];
                    bool invalid = !((bmw >> (i & 31)) & 1u);
                    if (invalid) {
                        int rank = s_wpre[i >> 5] +
                                   __popc(~bmw & ((1u << (i & 31)) - 1u));
                        if (rank < M && base + rank < CAND) {
                            ckey[base + rank] =
                                ((ull)ordered_float(-1.0f) << 32) |
                                (unsigned int)(~(unsigned int)i);
                        }
                    }
                }
                __syncthreads();
                if (tid == 0) {
                    int nc = s_cnt + M;
                    s_cnt = (nc > CAND) ? CAND : nc;
                }
                __syncthreads();
            } else {
                s_fallback = 1;   // pathological; handled below
            }
        }
    }
    __syncthreads();

    // ---- pathological full-exact fallback (correct, slow, not expected) ----
    if (s_fallback) {
        float* sc = g_scores + b * NA;
        for (int i = tid; i < NA; i += 512) {
            int HW, W, p, lvl; float stride;
            level_of(i, HW, W, stride, p, lvl);
            const float* cls = CLS[lvl];
            const float* obj = OBJ[lvl];
            float o  = obj[b * HW + p];
            float c0 = cls[(b * 2 + 0) * HW + p];
            float c1 = cls[(b * 2 + 1) * HW + p];
            float smax = __fmul_rn(sig_e(o), sig_e(fmaxf(c0, c1)));
            sc[i] = (smax > SCORE_THRESH) ? smax : -1.0f;
        }
        if (tid == 0) { s_prefix = 0ull; s_k = TOPK; s_cnt = 0; }
        __syncthreads();
        for (int pp = 7; pp >= 0; --pp) {
            for (int d = tid; d < 256; d += 512) hist[d] = 0;
            __syncthreads();
            ull pref = s_prefix;
            int sh = (pp + 1) * 8;
            for (int i = tid; i < NA; i += 512) {
                ull key = ((ull)ordered_float(sc[i]) << 32) |
                          (unsigned int)(~(unsigned int)i);
                bool match = (pp == 7) || ((key >> sh) == (pref >> sh));
                if (match) atomicAdd(&hist[(unsigned int)(key >> (pp * 8)) & 0xFFu], 1);
            }
            __syncthreads();
            if (tid == 0) {
                int k = s_k;
                for (int d = 255; d >= 0; --d) {
                    int c = hist[d];
                    if (k <= c) { s_prefix = pref | ((ull)d << (pp * 8)); break; }
                    k -= c;
                }
                s_k = k;
            }
            __syncthreads();
        }
        ull pivot = s_prefix;
        for (int i = tid; i < NA; i += 512) {
            ull key = ((ull)ordered_float(sc[i]) << 32) |
                      (unsigned int)(~(unsigned int)i);
            if (key >= pivot) {
                int pos = atomicAdd(&s_cnt, 1);
                if (pos < CAND) ckey[pos] = key;
            }
        }
        __syncthreads();
    }

    // ---- pad + bitonic sort (descending), 1024 / 512 threads ----
    int cnt = s_cnt; if (cnt > CAND) cnt = CAND;
    for (int s = tid; s < CAND; s += 512)
        if (s >= cnt) ckey[s] = 0ull;
    __syncthreads();

    for (int k = 2; k <= CAND; k <<= 1) {
        for (int j = k >> 1; j > 0; j >>= 1) {
            #pragma unroll
            for (int qq = 0; qq < 2; ++qq) {
                int i = tid + qq * 512;
                int ixj = i ^ j;
                if (ixj > i) {
                    bool desc = ((i & k) == 0);
                    ull ka = ckey[i], kb = ckey[ixj];
                    if (desc ? (ka < kb) : (ka > kb)) { ckey[i] = kb; ckey[ixj] = ka; }
                }
            }
            __syncthreads();
        }
    }

    // ---- transition: grab my key, then repurpose shared for NMS ----
    ull myk = ckey[tid];
    __syncthreads();

    // ---- NMS (box + label decode for top-500 only) ----
    int r = tid;
    float4 bb = make_float4(0.f, 0.f, 0.f, 0.f);
    float  sc = -1.0f;
    int    lab = 0;
    bool   validf = false;

    if (r < TOPK) {
        int idx = (int)(~(unsigned int)myk);
        sc = inv_ordered((unsigned int)(myk >> 32));
        if ((unsigned int)idx >= (unsigned int)NA) idx = 0;   // defensive

        int HW, W, p, lvl; float stride;
        level_of(idx, HW, W, stride, p, lvl);
        const float* reg = REG[lvl];
        const float* cls = CLS[lvl];
        const float* obj = OBJ[lvl];
        int y = p / W;
        int x = p - y * W;

        // box decode (verified rounding sequence)
        float dx = reg[(b * 4 + 0) * HW + p];
        float dy = reg[(b * 4 + 1) * HW + p];
        float dw = reg[(b * 4 + 2) * HW + p];
        float dh = reg[(b * 4 + 3) * HW + p];
        float cx = __fmul_rn(__fadd_rn((float)x, sig_e(dx)), stride);
        float cy = __fmul_rn(__fadd_rn((float)y, sig_e(dy)), stride);
        float w  = __fmul_rn(exp_cr(dw), stride);
        float h  = __fmul_rn(exp_cr(dh), stride);
        float wh = __fdiv_rn(w, 2.0f);
        float hh = __fdiv_rn(h, 2.0f);
        bb.x = __fsub_rn(cx, wh);
        bb.y = __fsub_rn(cy, hh);
        bb.z = __fadd_rn(cx, wh);
        bb.w = __fadd_rn(cy, hh);

        // label (exact-band check)
        float c0 = cls[(b * 2 + 0) * HW + p];
        float c1 = cls[(b * 2 + 1) * HW + p];
        if (c1 > c0) {
            if (__fsub_rn(c1, c0) < 1e-3f) {
                float o   = obj[b * HW + p];
                float so2 = sig_e(o);
                float s0  = __fmul_rn(so2, sig_e(c0));
                float s1  = __fmul_rn(so2, sig_e(c1));
                lab = (s1 > s0) ? 1 : 0;
            } else {
                lab = 1;
            }
        }

        float off = __fmul_rn((float)lab, CLASS_OFFSET);
        float x1 = __fadd_rn(bb.x, off);
        float y1 = __fadd_rn(bb.y, off);
        float x2 = __fadd_rn(bb.z, off);
        float y2 = __fadd_rn(bb.w, off);
        sbox[r] = make_float4(x1, y1, x2, y2);
        sar[r]  = __fmul_rn(__fsub_rn(x2, x1), __fsub_rn(y2, y1));
        validf  = (sc > SCORE_THRESH);
    } else {
        sbox[r] = make_float4(0.f, 0.f, 0.f, 0.f);
        sar[r]  = 0.f;
    }

    unsigned vb = __ballot_sync(0xFFFFFFFFu, validf);
    if ((r & 31) == 0) s_validw[r >> 5] = vb;

    #pragma unroll
    for (int w = 0; w < 16; ++w) adj[r * 16 + w] = 0u;
    __syncthreads();

    // balanced half-pair enumeration (each unordered pair once)
    {
        float4 mb = sbox[r];
        float  ar = sar[r];
        int kmax = (r < 256) ? 256 : 255;
        for (int k = 1; k <= kmax; ++k) {
            int j = (r + k) & 511;
            float4 bj = sbox[j];
            float  aj = sar[j];
            float ix1 = fmaxf(mb.x, bj.x);
            float iy1 = fmaxf(mb.y, bj.y);
            float ix2 = fminf(mb.z, bj.z);
            float iy2 = fminf(mb.w, bj.w);
            float iw  = fmaxf(__fsub_rn(ix2, ix1), 0.f);
            float ih  = fmaxf(__fsub_rn(iy2, iy1), 0.f);
            float inter = __fmul_rn(iw, ih);
            float uniP  = __fadd_rn(__fsub_rn(__fadd_rn(ar, aj), inter), 1e-7f);
            float t    = __fmul_rn(0.5f, uniP);
            float diff = __fsub_rn(inter, t);
            bool hit;
            if (fabsf(diff) <= __fmul_rn(1e-6f, t)) {
                float iou = __fdiv_rn(inter, uniP);   // exact decision in guard band
                hit = (iou >= NMS_THRESH);
            } else {
                hit = (diff > 0.f);
            }
            if (hit) {
                atomicOr(&adj[r * 16 + (j >> 5)], 1u << (j & 31));
                atomicOr(&adj[j * 16 + (r >> 5)], 1u << (r & 31));
            }
        }
    }
    __syncthreads();

    // serial greedy on warp 0 with one-ahead adjacency prefetch
    if (r < 32) {
        int lane = r;
        unsigned avail   = (lane < 16) ? s_validw[lane]     : 0u;
        unsigned nextadj = (lane < 16) ? adj[0 * 16 + lane] : 0u;
        for (int i = 0; i < TOPK; ++i) {
            unsigned myadj = nextadj;
            nextadj = (lane < 16 && i + 1 < 512) ? adj[(i + 1) * 16 + lane] : 0u;
            unsigned aw = __shfl_sync(0xFFFFFFFFu, avail, i >> 5);
            bool keep_i = (aw >> (i & 31)) & 1u;
            if (lane == 0) skeep[i] = keep_i ? 1 : 0;
            if (keep_i) avail &= ~myadj;
        }
    }
    __syncthreads();

    // outputs: [boxes (B*500*4)] [scores] [labels] [keep]
    if (r < TOPK) {
        bool kp = skeep[r] != 0;
        int row = b * TOPK + r;
        float* ob = out + row * 4;
        ob[0] = kp ? bb.x : 0.f;
        ob[1] = kp ? bb.y : 0.f;
        ob[2] = kp ? bb.z : 0.f;
        ob[3] = kp ? bb.w : 0.f;
        const int SBASE = B * TOPK * 4;
        const int LBASE = SBASE + B * TOPK;
        const int KBASE = LBASE + B * TOPK;
        out[SBASE + row] = kp ? sc : 0.f;
        out[LBASE + row] = (float)lab;
        out[KBASE + row] = kp ? 1.f : 0.f;
    }
}

// --------------------------------------------------------------- launch ----
extern "C" void kernel_launch(void* const* d_in, const int* in_sizes, int n_in,
                              void* d_out, int out_size)
{
    const float* cls_p3 = (const float*)d_in[0];
    const float* reg_p3 = (const float*)d_in[1];
    const float* obj_p3 = (const float*)d_in[2];
    const float* cls_p4 = (const float*)d_in[3];
    const float* reg_p4 = (const float*)d_in[4];
    const float* obj_p4 = (const float*)d_in[5];
    const float* cls_p5 = (const float*)d_in[6];
    const float* reg_p5 = (const float*)d_in[7];
    const float* obj_p5 = (const float*)d_in[8];
    float* out = (float*)d_out;

    void* p_cnt = nullptr;  void* p_hist = nullptr;
    cudaGetSymbolAddress(&p_cnt,  g_cnt);
    cudaGetSymbolAddress(&p_hist, g_hist);
    cudaMemsetAsync(p_cnt,  0, B * sizeof(int), 0);
    cudaMemsetAsync(p_hist, 0, B * NBIN * sizeof(int), 0);

    dim3 dgrid(33, B);
    decode_approx_kernel<<<dgrid, 256>>>(cls_p3, obj_p3, cls_p4, obj_p4, cls_p5, obj_p5);
    select_nms_kernel<<<B, 512>>>(cls_p3, reg_p3, obj_p3,
                                  cls_p4, reg_p4, obj_p4,
                                  cls_p5, reg_p5, obj_p5, out);
}

// round 9
// speedup vs baseline: 3.8082x; 3.8082x over previous
#include <cuda_runtime.h>
#include <cuda_bf16.h>
#include <math.h>

// Problem constants
#define B 64
#define NA 33600            // 160*160 + 80*80 + 40*40
#define TOPK 500
#define CAND 1024           // candidate sort size
#define NBIN 1024           // linear histogram bins over (0.3, 1.0]
#define SCORE_THRESH 0.3f
#define NMS_THRESH 0.5f
#define CLASS_OFFSET 10000.0f

#define P3_END 25600
#define P4_END 32000

typedef unsigned long long ull;

// ---------------- scratch (only the pathological fallback touches this) ----
__device__ float g_scores[B * NA];

// ------------------------------------------------------------ exp/sigmoid --
// Correctly-rounded float exp via double exp (matches XLA:CPU expf).
// Verified bit-compatible in R4-R8 — DO NOT change.
__device__ __forceinline__ float exp_cr(float x) {
    return (float)exp((double)x);
}
__device__ __forceinline__ float sig_e(float x) {
    float e = exp_cr(-x);
    return __fdiv_rn(1.0f, __fadd_rn(1.0f, e));
}
// fast sigmoid for the approximate path (product abs err < ~3e-6)
__device__ __forceinline__ float sig_fast(float x) {
    return __fdividef(1.0f, 1.0f + __expf(-x));
}

__device__ __forceinline__ unsigned int ordered_float(float f) {
    unsigned int u = __float_as_uint(f);
    return (u & 0x80000000u) ? ~u : (u | 0x80000000u);
}
__device__ __forceinline__ float inv_ordered(unsigned int u) {
    return __uint_as_float((u & 0x80000000u) ? (u ^ 0x80000000u) : ~u);
}
// monotone linear bin over (0.3, 1.0]
__device__ __forceinline__ int bin_of(float s) {
    int q = (int)(__fmul_rn(__fsub_rn(s, 0.3f), 1462.857f));
    if (q < 0) q = 0;
    return (q > NBIN - 1) ? (NBIN - 1) : q;
}

__device__ __forceinline__ void level_of(int idx, int& HW, int& W, float& stride, int& p, int& lvl) {
    if (idx < P3_END)      { HW = 25600; W = 160; stride = 8.f;  p = idx;          lvl = 0; }
    else if (idx < P4_END) { HW = 6400;  W = 80;  stride = 16.f; p = idx - P3_END; lvl = 1; }
    else                   { HW = 1600;  W = 40;  stride = 32.f; p = idx - P4_END; lvl = 2; }
}

// =================== single fused kernel: scan + select + NMS ==============
__global__ __launch_bounds__(512, 1)
void fused_detect_kernel(const float* __restrict__ cls3,
                         const float* __restrict__ reg3,
                         const float* __restrict__ obj3,
                         const float* __restrict__ cls4,
                         const float* __restrict__ reg4,
                         const float* __restrict__ obj4,
                         const float* __restrict__ cls5,
                         const float* __restrict__ reg5,
                         const float* __restrict__ obj5,
                         float* __restrict__ out)
{
    // shared union:
    //  scan/select phase: sap[0,4K) cidx[4K,8K) ckey[8K,16K) hist[16K,20K)
    //  NMS phase:         sbox[0,8K) sar[8K,10K) adj[10K,42K)
    __shared__ __align__(16) unsigned char smem_raw[43008];
    float*  sap  = (float*)smem_raw;
    int*    cidx = (int*)(smem_raw + 4096);
    ull*    ckey = (ull*)(smem_raw + 8192);
    int*    hist = (int*)(smem_raw + 16384);
    float4* sbox = (float4*)smem_raw;
    float*  sar  = (float*)(smem_raw + 8192);
    unsigned int* adj = (unsigned int*)(smem_raw + 10240);

    __shared__ int  coarse[NBIN / 4];
    __shared__ int  s_qp, s_cnt, s_nvalid, s_fallback;
    __shared__ ull  s_prefix;
    __shared__ int  s_k;
    __shared__ unsigned int s_validw[16];
    __shared__ unsigned char skeep[512];
    __shared__ unsigned int s_vbm[32];     // valid bitmap over anchor idx [0,1024)
    __shared__ int  s_wpre[33];

    int b   = blockIdx.x;
    int tid = threadIdx.x;

    const float* CLS[3] = {cls3, cls4, cls5};
    const float* REG[3] = {reg3, reg4, reg5};
    const float* OBJ[3] = {obj3, obj4, obj5};

    for (int d = tid; d < NBIN; d += 512) hist[d] = 0;
    if (tid == 0) { s_cnt = 0; s_nvalid = 0; s_fallback = 0; }
    if (tid < 32) s_vbm[tid] = 0u;
    __syncthreads();

    // ---- phase 1: full-batch scan, approx scores, shared-atomic push ------
    for (int base = 0; base < NA; base += 2048) {
        int a = base + tid * 4;
        if (a < NA) {
            const float* cls; const float* obj; int HW, p;
            if (a < P3_END)      { cls = cls3; obj = obj3; HW = 25600; p = a; }
            else if (a < P4_END) { cls = cls4; obj = obj4; HW = 6400;  p = a - P3_END; }
            else                 { cls = cls5; obj = obj5; HW = 1600;  p = a - P4_END; }

            float4 o4  = *(const float4*)(obj + b * HW + p);
            float4 c04 = *(const float4*)(cls + (b * 2 + 0) * HW + p);
            float4 c14 = *(const float4*)(cls + (b * 2 + 1) * HW + p);
            float oo[4]  = {o4.x, o4.y, o4.z, o4.w};
            float cc0[4] = {c04.x, c04.y, c04.z, c04.w};
            float cc1[4] = {c14.x, c14.y, c14.z, c14.w};

            #pragma unroll
            for (int j = 0; j < 4; ++j) {
                float cm = fmaxf(cc0[j], cc1[j]);
                float v  = sig_fast(oo[j]) * sig_fast(cm);
                if (v >= 0.29999f) {          // exact>0.3 ⇒ approx clears this
                    int pos = atomicAdd(&s_cnt, 1);
                    if (pos < CAND) { cidx[pos] = a + j; sap[pos] = v; }
                    atomicAdd(&hist[bin_of(v)], 1);
                }
            }
        }
    }
    __syncthreads();
    int cnt_all = s_cnt;

    // ---- phase 2 (rare): too many approx-survivors -> histogram re-gather -
    if (cnt_all > CAND) {
        if (tid < NBIN / 4)
            coarse[tid] = hist[4 * tid] + hist[4 * tid + 1] + hist[4 * tid + 2] + hist[4 * tid + 3];
        __syncthreads();
        if (tid == 0) {
            int cum = 0, qp = 0;
            for (int g = NBIN / 4 - 1; g >= 0; --g) {
                if (cum + coarse[g] >= TOPK) {
                    for (int d = 4 * g + 3; d >= 4 * g; --d) {
                        if (cum + hist[d] >= TOPK) { qp = d; break; }
                        cum += hist[d];
                    }
                    break;
                }
                cum += coarse[g];
            }
            s_qp = (qp > 0) ? qp - 1 : 0;   // 1-bin relaxation covers approx err
            s_cnt = 0;
        }
        __syncthreads();
        int qp = s_qp;
        for (int base = 0; base < NA; base += 2048) {
            int a = base + tid * 4;
            if (a < NA) {
                const float* cls; const float* obj; int HW, p;
                if (a < P3_END)      { cls = cls3; obj = obj3; HW = 25600; p = a; }
                else if (a < P4_END) { cls = cls4; obj = obj4; HW = 6400;  p = a - P3_END; }
                else                 { cls = cls5; obj = obj5; HW = 1600;  p = a - P4_END; }
                float4 o4  = *(const float4*)(obj + b * HW + p);
                float4 c04 = *(const float4*)(cls + (b * 2 + 0) * HW + p);
                float4 c14 = *(const float4*)(cls + (b * 2 + 1) * HW + p);
                float oo[4]  = {o4.x, o4.y, o4.z, o4.w};
                float cc0[4] = {c04.x, c04.y, c04.z, c04.w};
                float cc1[4] = {c14.x, c14.y, c14.z, c14.w};
                #pragma unroll
                for (int j = 0; j < 4; ++j) {
                    float cm = fmaxf(cc0[j], cc1[j]);
                    float v  = sig_fast(oo[j]) * sig_fast(cm);
                    if (v >= 0.29999f && bin_of(v) >= qp) {
                        int pos = atomicAdd(&s_cnt, 1);
                        if (pos < CAND) { cidx[pos] = a + j; sap[pos] = v; }
                        else            s_fallback = 1;   // pathological ties
                    }
                }
            }
        }
        __syncthreads();
    }

    // ---- phase 3: exact scores for gathered candidates --------------------
    if (!s_fallback) {
        int m = s_cnt; if (m > CAND) m = CAND;
        for (int it = tid; it < m; it += 512) {
            int idx = cidx[it];
            int HW, W, p, lvl; float stride;
            level_of(idx, HW, W, stride, p, lvl);
            const float* cls = CLS[lvl];
            const float* obj = OBJ[lvl];
            float o  = obj[b * HW + p];
            float c0 = cls[(b * 2 + 0) * HW + p];
            float c1 = cls[(b * 2 + 1) * HW + p];
            float cmax = fmaxf(c0, c1);
            float smax = __fmul_rn(sig_e(o), sig_e(cmax));  // == max(s0,s1)
            ull key = 0ull;
            if (smax > SCORE_THRESH) {
                key = ((ull)ordered_float(smax) << 32) |
                      (unsigned int)(~(unsigned int)idx);
                atomicAdd(&s_nvalid, 1);
                if ((unsigned int)idx < 1024u)
                    atomicOr(&s_vbm[idx >> 5], 1u << (idx & 31));
            }
            ckey[it] = key;
        }
        __syncthreads();

        if (s_nvalid < TOPK) {
            int M = TOPK - s_nvalid;
            // pad path valid only when candidate set == ALL approx-survivors
            // (then every exact-valid idx<1024 is in the bitmap) and room exists
            if (cnt_all <= CAND && s_cnt + M <= CAND) {
                if (tid == 0) {
                    int acc = 0;
                    for (int w = 0; w < 32; ++w) {
                        s_wpre[w] = acc;
                        acc += 32 - __popc(s_vbm[w]);
                    }
                    s_wpre[32] = acc;
                }
                __syncthreads();
                int base2 = s_cnt;
                #pragma unroll
                for (int q2 = 0; q2 < 2; ++q2) {
                    int i = tid + q2 * 512;
                    unsigned int bmw = s_vbm[i >> 5];
                    bool invalid = !((bmw >> (i & 31)) & 1u);
                    if (invalid) {
                        int rank = s_wpre[i >> 5] +
                                   __popc(~bmw & ((1u << (i & 31)) - 1u));
                        if (rank < M) {
                            ckey[base2 + rank] =
                                ((ull)ordered_float(-1.0f) << 32) |
                                (unsigned int)(~(unsigned int)i);
                        }
                    }
                }
                __syncthreads();
                if (tid == 0) s_cnt = base2 + M;
                __syncthreads();
            } else {
                s_fallback = 1;
            }
        }
    }
    __syncthreads();

    // ---- pathological full-exact fallback (correct, slow, unexpected) -----
    if (s_fallback) {
        float* sc = g_scores + b * NA;
        for (int i = tid; i < NA; i += 512) {
            int HW, W, p, lvl; float stride;
            level_of(i, HW, W, stride, p, lvl);
            const float* cls = CLS[lvl];
            const float* obj = OBJ[lvl];
            float o  = obj[b * HW + p];
            float c0 = cls[(b * 2 + 0) * HW + p];
            float c1 = cls[(b * 2 + 1) * HW + p];
            float smax = __fmul_rn(sig_e(o), sig_e(fmaxf(c0, c1)));
            sc[i] = (smax > SCORE_THRESH) ? smax : -1.0f;
        }
        if (tid == 0) { s_prefix = 0ull; s_k = TOPK; s_cnt = 0; }
        __syncthreads();
        for (int pp = 7; pp >= 0; --pp) {
            for (int d = tid; d < 256; d += 512) hist[d] = 0;
            __syncthreads();
            ull pref = s_prefix;
            int sh = (pp + 1) * 8;
            for (int i = tid; i < NA; i += 512) {
                ull key = ((ull)ordered_float(sc[i]) << 32) |
                          (unsigned int)(~(unsigned int)i);
                bool match = (pp == 7) || ((key >> sh) == (pref >> sh));
                if (match) atomicAdd(&hist[(unsigned int)(key >> (pp * 8)) & 0xFFu], 1);
            }
            __syncthreads();
            if (tid == 0) {
                int k = s_k;
                for (int d = 255; d >= 0; --d) {
                    int c = hist[d];
                    if (k <= c) { s_prefix = pref | ((ull)d << (pp * 8)); break; }
                    k -= c;
                }
                s_k = k;
            }
            __syncthreads();
        }
        ull pivot = s_prefix;
        for (int i = tid; i < NA; i += 512) {
            ull key = ((ull)ordered_float(sc[i]) << 32) |
                      (unsigned int)(~(unsigned int)i);
            if (key >= pivot) {
                int pos = atomicAdd(&s_cnt, 1);
                if (pos < CAND) ckey[pos] = key;
            }
        }
        __syncthreads();
    }

    // ---- sort: pad to CAND, bitonic descending, 1024 / 512 threads --------
    int cnt = s_cnt; if (cnt > CAND) cnt = CAND;
    for (int s = tid; s < CAND; s += 512)
        if (s >= cnt) ckey[s] = 0ull;
    __syncthreads();

    for (int k = 2; k <= CAND; k <<= 1) {
        for (int j = k >> 1; j > 0; j >>= 1) {
            #pragma unroll
            for (int qq = 0; qq < 2; ++qq) {
                int i = tid + qq * 512;
                int ixj = i ^ j;
                if (ixj > i) {
                    bool desc = ((i & k) == 0);
                    ull ka = ckey[i], kb = ckey[ixj];
                    if (desc ? (ka < kb) : (ka > kb)) { ckey[i] = kb; ckey[ixj] = ka; }
                }
            }
            __syncthreads();
        }
    }

    // ---- transition to NMS phase ----
    ull myk = ckey[tid];
    __syncthreads();

    int r = tid;
    float4 bb = make_float4(0.f, 0.f, 0.f, 0.f);
    float  sc = -1.0f;
    int    lab = 0;
    bool   validf = false;

    if (r < TOPK) {
        int idx = (int)(~(unsigned int)myk);
        sc = inv_ordered((unsigned int)(myk >> 32));
        if ((unsigned int)idx >= (unsigned int)NA) idx = 0;   // defensive

        int HW, W, p, lvl; float stride;
        level_of(idx, HW, W, stride, p, lvl);
        const float* reg = REG[lvl];
        const float* cls = CLS[lvl];
        const float* obj = OBJ[lvl];
        int y = p / W;
        int x = p - y * W;

        float dx = reg[(b * 4 + 0) * HW + p];
        float dy = reg[(b * 4 + 1) * HW + p];
        float dw = reg[(b * 4 + 2) * HW + p];
        float dh = reg[(b * 4 + 3) * HW + p];
        float cx = __fmul_rn(__fadd_rn((float)x, sig_e(dx)), stride);
        float cy = __fmul_rn(__fadd_rn((float)y, sig_e(dy)), stride);
        float w  = __fmul_rn(exp_cr(dw), stride);
        float h  = __fmul_rn(exp_cr(dh), stride);
        float wh = __fdiv_rn(w, 2.0f);
        float hh = __fdiv_rn(h, 2.0f);
        bb.x = __fsub_rn(cx, wh);
        bb.y = __fsub_rn(cy, hh);
        bb.z = __fadd_rn(cx, wh);
        bb.w = __fadd_rn(cy, hh);

        float c0 = cls[(b * 2 + 0) * HW + p];
        float c1 = cls[(b * 2 + 1) * HW + p];
        if (c1 > c0) {
            if (__fsub_rn(c1, c0) < 1e-3f) {
                float o   = obj[b * HW + p];
                float so2 = sig_e(o);
                float s0  = __fmul_rn(so2, sig_e(c0));
                float s1  = __fmul_rn(so2, sig_e(c1));
                lab = (s1 > s0) ? 1 : 0;
            } else {
                lab = 1;
            }
        }

        float off = __fmul_rn((float)lab, CLASS_OFFSET);
        float x1 = __fadd_rn(bb.x, off);
        float y1 = __fadd_rn(bb.y, off);
        float x2 = __fadd_rn(bb.z, off);
        float y2 = __fadd_rn(bb.w, off);
        sbox[r] = make_float4(x1, y1, x2, y2);
        sar[r]  = __fmul_rn(__fsub_rn(x2, x1), __fsub_rn(y2, y1));
        validf  = (sc > SCORE_THRESH);
    } else {
        sbox[r] = make_float4(0.f, 0.f, 0.f, 0.f);
        sar[r]  = 0.f;
    }

    unsigned vb = __ballot_sync(0xFFFFFFFFu, validf);
    if ((r & 31) == 0) s_validw[r >> 5] = vb;

    #pragma unroll
    for (int w = 0; w < 16; ++w) adj[r * 16 + w] = 0u;
    __syncthreads();

    // balanced half-pair enumeration (each unordered pair once)
    {
        float4 mb = sbox[r];
        float  ar = sar[r];
        int kmax = (r < 256) ? 256 : 255;
        for (int k = 1; k <= kmax; ++k) {
            int j = (r + k) & 511;
            float4 bj = sbox[j];
            float  aj = sar[j];
            float ix1 = fmaxf(mb.x, bj.x);
            float iy1 = fmaxf(mb.y, bj.y);
            float ix2 = fminf(mb.z, bj.z);
            float iy2 = fminf(mb.w, bj.w);
            float iw  = fmaxf(__fsub_rn(ix2, ix1), 0.f);
            float ih  = fmaxf(__fsub_rn(iy2, iy1), 0.f);
            float inter = __fmul_rn(iw, ih);
            float uniP  = __fadd_rn(__fsub_rn(__fadd_rn(ar, aj), inter), 1e-7f);
            float t    = __fmul_rn(0.5f, uniP);
            float diff = __fsub_rn(inter, t);
            bool hit;
            if (fabsf(diff) <= __fmul_rn(1e-6f, t)) {
                float iou = __fdiv_rn(inter, uniP);   // exact decision in band
                hit = (iou >= NMS_THRESH);
            } else {
                hit = (diff > 0.f);
            }
            if (hit) {
                atomicOr(&adj[r * 16 + (j >> 5)], 1u << (j & 31));
                atomicOr(&adj[j * 16 + (r >> 5)], 1u << (r & 31));
            }
        }
    }
    __syncthreads();

    // serial greedy on warp 0 with one-ahead adjacency prefetch
    if (r < 32) {
        int lane = r;
        unsigned avail   = (lane < 16) ? s_validw[lane]     : 0u;
        unsigned nextadj = (lane < 16) ? adj[0 * 16 + lane] : 0u;
        for (int i = 0; i < TOPK; ++i) {
            unsigned myadj = nextadj;
            nextadj = (lane < 16 && i + 1 < 512) ? adj[(i + 1) * 16 + lane] : 0u;
            unsigned aw = __shfl_sync(0xFFFFFFFFu, avail, i >> 5);
            bool keep_i = (aw >> (i & 31)) & 1u;
            if (lane == 0) skeep[i] = keep_i ? 1 : 0;
            if (keep_i) avail &= ~myadj;
        }
    }
    __syncthreads();

    // outputs: [boxes (B*500*4)] [scores] [labels] [keep]
    if (r < TOPK) {
        bool kp = skeep[r] != 0;
        int row = b * TOPK + r;
        float* ob = out + row * 4;
        ob[0] = kp ? bb.x : 0.f;
        ob[1] = kp ? bb.y : 0.f;
        ob[2] = kp ? bb.z : 0.f;
        ob[3] = kp ? bb.w : 0.f;
        const int SBASE = B * TOPK * 4;
        const int LBASE = SBASE + B * TOPK;
        const int KBASE = LBASE + B * TOPK;
        out[SBASE + row] = kp ? sc : 0.f;
        out[LBASE + row] = (float)lab;
        out[KBASE + row] = kp ? 1.f : 0.f;
    }
}

// --------------------------------------------------------------- launch ----
extern "C" void kernel_launch(void* const* d_in, const int* in_sizes, int n_in,
                              void* d_out, int out_size)
{
    const float* cls_p3 = (const float*)d_in[0];
    const float* reg_p3 = (const float*)d_in[1];
    const float* obj_p3 = (const float*)d_in[2];
    const float* cls_p4 = (const float*)d_in[3];
    const float* reg_p4 = (const float*)d_in[4];
    const float* obj_p4 = (const float*)d_in[5];
    const float* cls_p5 = (const float*)d_in[6];
    const float* reg_p5 = (const float*)d_in[7];
    const float* obj_p5 = (const float*)d_in[8];
    float* out = (float*)d_out;

    fused_detect_kernel<<<B, 512>>>(cls_p3, reg_p3, obj_p3,
                                    cls_p4, reg_p4, obj_p4,
                                    cls_p5, reg_p5, obj_p5, out);
}

// round 10
// speedup vs baseline: 4.8395x; 1.2708x over previous
#include <cuda_runtime.h>
#include <cuda_bf16.h>
#include <math.h>

// Problem constants
#define B 64
#define NA 33600            // 160*160 + 80*80 + 40*40
#define TOPK 500
#define CAND 1024           // candidate sort size
#define NBIN 1024           // linear histogram bins over (0.3, 1.0]
#define SCORE_THRESH 0.3f
#define NMS_THRESH 0.5f
#define CLASS_OFFSET 10000.0f

#define P3_END 25600
#define P4_END 32000

typedef unsigned long long ull;

// ---------------- scratch (static device allocations; no runtime alloc) ----
__device__ float g_scores[B * NA];      // only the pathological fallback
__device__ ull   g_cand[B * NA];        // per-batch approx candidate keys
__device__ int   g_cnt[B];
__device__ int   g_hist[B][NBIN];

// ------------------------------------------------------------ exp/sigmoid --
// Correctly-rounded float exp via double exp (matches XLA:CPU expf).
// Verified bit-compatible in R4-R9 — DO NOT change.
__device__ __forceinline__ float exp_cr(float x) {
    return (float)exp((double)x);
}
__device__ __forceinline__ float sig_e(float x) {
    float e = exp_cr(-x);
    return __fdiv_rn(1.0f, __fadd_rn(1.0f, e));
}
// fast sigmoid for the approximate path (product abs err < ~3e-6)
__device__ __forceinline__ float sig_fast(float x) {
    return __fdividef(1.0f, 1.0f + __expf(-x));
}

__device__ __forceinline__ unsigned int ordered_float(float f) {
    unsigned int u = __float_as_uint(f);
    return (u & 0x80000000u) ? ~u : (u | 0x80000000u);
}
__device__ __forceinline__ float inv_ordered(unsigned int u) {
    return __uint_as_float((u & 0x80000000u) ? (u ^ 0x80000000u) : ~u);
}
__device__ __forceinline__ int bin_of(float s) {
    int q = (int)(__fmul_rn(__fsub_rn(s, 0.3f), 1462.857f));
    if (q < 0) q = 0;
    return (q > NBIN - 1) ? (NBIN - 1) : q;
}

__device__ __forceinline__ void level_of(int idx, int& HW, int& W, float& stride, int& p, int& lvl) {
    if (idx < P3_END)      { HW = 25600; W = 160; stride = 8.f;  p = idx;          lvl = 0; }
    else if (idx < P4_END) { HW = 6400;  W = 80;  stride = 16.f; p = idx - P3_END; lvl = 1; }
    else                   { HW = 1600;  W = 40;  stride = 32.f; p = idx - P4_END; lvl = 2; }
}

// =================== kernel 1: highly-parallel approx scan =================
// grid (17, 64) x 512 threads; each thread handles one float4 group.
__global__ __launch_bounds__(512)
void scan_kernel(const float* __restrict__ cls3,
                 const float* __restrict__ obj3,
                 const float* __restrict__ cls4,
                 const float* __restrict__ obj4,
                 const float* __restrict__ cls5,
                 const float* __restrict__ obj5)
{
    __shared__ int   s_idx[2048];
    __shared__ float s_ap[2048];
    __shared__ int   s_hist[NBIN];
    __shared__ int   s_n, s_base;

    int b   = blockIdx.y;
    int tid = threadIdx.x;

    for (int d = tid; d < NBIN; d += 512) s_hist[d] = 0;
    if (tid == 0) s_n = 0;
    __syncthreads();

    int t = blockIdx.x * 512 + tid;      // float4-group id
    int a = t * 4;
    if (a < NA) {
        const float* cls; const float* obj; int HW, p;
        if (a < P3_END)      { cls = cls3; obj = obj3; HW = 25600; p = a; }
        else if (a < P4_END) { cls = cls4; obj = obj4; HW = 6400;  p = a - P3_END; }
        else                 { cls = cls5; obj = obj5; HW = 1600;  p = a - P4_END; }

        float4 o4  = *(const float4*)(obj + b * HW + p);
        float4 c04 = *(const float4*)(cls + (b * 2 + 0) * HW + p);
        float4 c14 = *(const float4*)(cls + (b * 2 + 1) * HW + p);
        float oo[4]  = {o4.x, o4.y, o4.z, o4.w};
        float cc0[4] = {c04.x, c04.y, c04.z, c04.w};
        float cc1[4] = {c14.x, c14.y, c14.z, c14.w};

        #pragma unroll
        for (int j = 0; j < 4; ++j) {
            float cm = fmaxf(cc0[j], cc1[j]);
            float v  = sig_fast(oo[j]) * sig_fast(cm);
            if (v >= 0.29999f) {             // exact>0.3 ⇒ approx clears this
                int pos = atomicAdd(&s_n, 1);          // shared atomic (cheap)
                s_idx[pos] = a + j; s_ap[pos] = v;
                atomicAdd(&s_hist[bin_of(v)], 1);
            }
        }
    }
    __syncthreads();

    if (tid == 0 && s_n) s_base = atomicAdd(&g_cnt[b], s_n);  // ONE global atomic
    __syncthreads();

    int n = s_n;
    for (int i = tid; i < n; i += 512) {
        g_cand[b * NA + s_base + i] =
            ((ull)ordered_float(s_ap[i]) << 32) |
            (unsigned int)(~(unsigned int)s_idx[i]);
    }
    for (int d = tid; d < NBIN; d += 512) {
        int h = s_hist[d];
        if (h) atomicAdd(&g_hist[b][d], h);   // sparse: only bins with survivors
    }
}

// =================== kernel 2: select (exact top-k) + NMS, 1024 thr ========
__global__ __launch_bounds__(1024, 1)
void select_nms_kernel(const float* __restrict__ cls3,
                       const float* __restrict__ reg3,
                       const float* __restrict__ obj3,
                       const float* __restrict__ cls4,
                       const float* __restrict__ reg4,
                       const float* __restrict__ obj4,
                       const float* __restrict__ cls5,
                       const float* __restrict__ reg5,
                       const float* __restrict__ obj5,
                       float* __restrict__ out)
{
    // shared union:
    //  select phase: hist[0,4K) cidx[4K,8K) ckey[8K,16K)
    //  NMS phase:    sbox[0,8K) sar[8K,10K) adj[10K,42K)
    __shared__ __align__(16) unsigned char smem_raw[43008];
    int*    hist = (int*)smem_raw;
    int*    cidx = (int*)(smem_raw + 4096);
    ull*    ckey = (ull*)(smem_raw + 8192);
    float4* sbox = (float4*)smem_raw;
    float*  sar  = (float*)(smem_raw + 8192);
    unsigned int* adj = (unsigned int*)(smem_raw + 10240);

    __shared__ int  coarse[NBIN / 4];
    __shared__ int  s_qp, s_cnt, s_nvalid, s_fallback;
    __shared__ ull  s_prefix;
    __shared__ int  s_k;
    __shared__ unsigned int s_validw[16];
    __shared__ unsigned char skeep[512];
    __shared__ unsigned int s_vbm[32];
    __shared__ int  s_wpre[33];

    int b   = blockIdx.x;
    int tid = threadIdx.x;
    const int NT = 1024;
    int cnt_all = g_cnt[b];

    const float* CLS[3] = {cls3, cls4, cls5};
    const float* REG[3] = {reg3, reg4, reg5};
    const float* OBJ[3] = {obj3, obj4, obj5};

    if (tid == 0) { s_cnt = 0; s_nvalid = 0; s_fallback = 0; }
    if (tid < 32) s_vbm[tid] = 0u;
    __syncthreads();

    const ull* cl = g_cand + b * NA;

    if (cnt_all <= CAND) {
        // small path: take ALL candidates
        for (int i = tid; i < cnt_all; i += NT)
            cidx[i] = (int)(~(unsigned int)cl[i]);
        if (tid == 0) s_cnt = cnt_all;
        __syncthreads();
    } else {
        // histogram path
        for (int d = tid; d < NBIN; d += NT) hist[d] = g_hist[b][d];
        __syncthreads();
        if (tid < NBIN / 4)
            coarse[tid] = hist[4 * tid] + hist[4 * tid + 1] + hist[4 * tid + 2] + hist[4 * tid + 3];
        __syncthreads();
        if (tid == 0) {
            int cum = 0, qp = 0;
            for (int g = NBIN / 4 - 1; g >= 0; --g) {
                if (cum + coarse[g] >= TOPK) {
                    for (int d = 4 * g + 3; d >= 4 * g; --d) {
                        if (cum + hist[d] >= TOPK) { qp = d; break; }
                        cum += hist[d];
                    }
                    break;
                }
                cum += coarse[g];
            }
            s_qp = (qp > 0) ? qp - 1 : 0;
        }
        __syncthreads();
        int qp = s_qp;
        for (int i = tid; i < cnt_all; i += NT) {
            ull key = cl[i];
            float s = inv_ordered((unsigned int)(key >> 32));
            if (bin_of(s) >= qp) {
                int pos = atomicAdd(&s_cnt, 1);
                if (pos < CAND) cidx[pos] = (int)(~(unsigned int)key);
                else            s_fallback = 1;
            }
        }
        __syncthreads();
    }

    // exact scores for gathered candidates
    if (!s_fallback) {
        int m = s_cnt; if (m > CAND) m = CAND;
        for (int it = tid; it < m; it += NT) {
            int idx = cidx[it];
            int HW, W, p, lvl; float stride;
            level_of(idx, HW, W, stride, p, lvl);
            const float* cls = CLS[lvl];
            const float* obj = OBJ[lvl];
            float o  = obj[b * HW + p];
            float c0 = cls[(b * 2 + 0) * HW + p];
            float c1 = cls[(b * 2 + 1) * HW + p];
            float cmax = fmaxf(c0, c1);
            float smax = __fmul_rn(sig_e(o), sig_e(cmax));  // == max(s0,s1)
            ull key = 0ull;
            if (smax > SCORE_THRESH) {
                key = ((ull)ordered_float(smax) << 32) |
                      (unsigned int)(~(unsigned int)idx);
                atomicAdd(&s_nvalid, 1);
                if ((unsigned int)idx < 1024u)
                    atomicOr(&s_vbm[idx >> 5], 1u << (idx & 31));
            }
            ckey[it] = key;
        }
        __syncthreads();

        if (s_nvalid < TOPK) {
            int M = TOPK - s_nvalid;
            if (cnt_all <= CAND && s_cnt + M <= CAND) {
                if (tid == 0) {
                    int acc = 0;
                    for (int w = 0; w < 32; ++w) {
                        s_wpre[w] = acc;
                        acc += 32 - __popc(s_vbm[w]);
                    }
                    s_wpre[32] = acc;
                }
                __syncthreads();
                int base2 = s_cnt;
                {
                    int i = tid;   // NT == 1024 covers [0,1024)
                    unsigned int bmw = s_vbm[i >> 5];
                    bool invalid = !((bmw >> (i & 31)) & 1u);
                    if (invalid) {
                        int rank = s_wpre[i >> 5] +
                                   __popc(~bmw & ((1u << (i & 31)) - 1u));
                        if (rank < M) {
                            ckey[base2 + rank] =
                                ((ull)ordered_float(-1.0f) << 32) |
                                (unsigned int)(~(unsigned int)i);
                        }
                    }
                }
                __syncthreads();
                if (tid == 0) s_cnt = base2 + M;
                __syncthreads();
            } else {
                s_fallback = 1;
            }
        }
    }
    __syncthreads();

    // pathological full-exact fallback (correct, slow, unexpected)
    if (s_fallback) {
        float* sc = g_scores + b * NA;
        for (int i = tid; i < NA; i += NT) {
            int HW, W, p, lvl; float stride;
            level_of(i, HW, W, stride, p, lvl);
            const float* cls = CLS[lvl];
            const float* obj = OBJ[lvl];
            float o  = obj[b * HW + p];
            float c0 = cls[(b * 2 + 0) * HW + p];
            float c1 = cls[(b * 2 + 1) * HW + p];
            float smax = __fmul_rn(sig_e(o), sig_e(fmaxf(c0, c1)));
            sc[i] = (smax > SCORE_THRESH) ? smax : -1.0f;
        }
        if (tid == 0) { s_prefix = 0ull; s_k = TOPK; s_cnt = 0; }
        __syncthreads();
        for (int pp = 7; pp >= 0; --pp) {
            for (int d = tid; d < 256; d += NT) hist[d] = 0;
            __syncthreads();
            ull pref = s_prefix;
            int sh = (pp + 1) * 8;
            for (int i = tid; i < NA; i += NT) {
                ull key = ((ull)ordered_float(sc[i]) << 32) |
                          (unsigned int)(~(unsigned int)i);
                bool match = (pp == 7) || ((key >> sh) == (pref >> sh));
                if (match) atomicAdd(&hist[(unsigned int)(key >> (pp * 8)) & 0xFFu], 1);
            }
            __syncthreads();
            if (tid == 0) {
                int k = s_k;
                for (int d = 255; d >= 0; --d) {
                    int c = hist[d];
                    if (k <= c) { s_prefix = pref | ((ull)d << (pp * 8)); break; }
                    k -= c;
                }
                s_k = k;
            }
            __syncthreads();
        }
        ull pivot = s_prefix;
        for (int i = tid; i < NA; i += NT) {
            ull key = ((ull)ordered_float(sc[i]) << 32) |
                      (unsigned int)(~(unsigned int)i);
            if (key >= pivot) {
                int pos = atomicAdd(&s_cnt, 1);
                if (pos < CAND) ckey[pos] = key;
            }
        }
        __syncthreads();
    }

    // pad + bitonic sort (descending), 1024 elems / 1024 threads
    int cnt = s_cnt; if (cnt > CAND) cnt = CAND;
    if (tid >= cnt) ckey[tid] = 0ull;
    __syncthreads();

    for (int k = 2; k <= CAND; k <<= 1) {
        for (int j = k >> 1; j > 0; j >>= 1) {
            int i = tid;
            int ixj = i ^ j;
            if (ixj > i) {
                bool desc = ((i & k) == 0);
                ull ka = ckey[i], kb = ckey[ixj];
                if (desc ? (ka < kb) : (ka > kb)) { ckey[i] = kb; ckey[ixj] = ka; }
            }
            __syncthreads();
        }
    }

    // transition to NMS phase
    ull myk = ckey[tid];
    __syncthreads();

    int r = tid;
    float4 bb = make_float4(0.f, 0.f, 0.f, 0.f);
    float  sc = -1.0f;
    int    lab = 0;
    bool   validf = false;

    if (r < TOPK) {
        int idx = (int)(~(unsigned int)myk);
        sc = inv_ordered((unsigned int)(myk >> 32));
        if ((unsigned int)idx >= (unsigned int)NA) idx = 0;   // defensive

        int HW, W, p, lvl; float stride;
        level_of(idx, HW, W, stride, p, lvl);
        const float* reg = REG[lvl];
        const float* cls = CLS[lvl];
        const float* obj = OBJ[lvl];
        int y = p / W;
        int x = p - y * W;

        float dx = reg[(b * 4 + 0) * HW + p];
        float dy = reg[(b * 4 + 1) * HW + p];
        float dw = reg[(b * 4 + 2) * HW + p];
        float dh = reg[(b * 4 + 3) * HW + p];
        float cx = __fmul_rn(__fadd_rn((float)x, sig_e(dx)), stride);
        float cy = __fmul_rn(__fadd_rn((float)y, sig_e(dy)), stride);
        float w  = __fmul_rn(exp_cr(dw), stride);
        float h  = __fmul_rn(exp_cr(dh), stride);
        float wh = __fdiv_rn(w, 2.0f);
        float hh = __fdiv_rn(h, 2.0f);
        bb.x = __fsub_rn(cx, wh);
        bb.y = __fsub_rn(cy, hh);
        bb.z = __fadd_rn(cx, wh);
        bb.w = __fadd_rn(cy, hh);

        float c0 = cls[(b * 2 + 0) * HW + p];
        float c1 = cls[(b * 2 + 1) * HW + p];
        if (c1 > c0) {
            if (__fsub_rn(c1, c0) < 1e-3f) {
                float o   = obj[b * HW + p];
                float so2 = sig_e(o);
                float s0  = __fmul_rn(so2, sig_e(c0));
                float s1  = __fmul_rn(so2, sig_e(c1));
                lab = (s1 > s0) ? 1 : 0;
            } else {
                lab = 1;
            }
        }

        float off = __fmul_rn((float)lab, CLASS_OFFSET);
        float x1 = __fadd_rn(bb.x, off);
        float y1 = __fadd_rn(bb.y, off);
        float x2 = __fadd_rn(bb.z, off);
        float y2 = __fadd_rn(bb.w, off);
        sbox[r] = make_float4(x1, y1, x2, y2);
        sar[r]  = __fmul_rn(__fsub_rn(x2, x1), __fsub_rn(y2, y1));
        validf  = (sc > SCORE_THRESH);
    } else if (r < 512) {
        sbox[r] = make_float4(0.f, 0.f, 0.f, 0.f);
        sar[r]  = 0.f;
    }

    unsigned vb = __ballot_sync(0xFFFFFFFFu, validf);
    if (r < 512 && (r & 31) == 0) s_validw[r >> 5] = vb;

    #pragma unroll
    for (int w = 0; w < 8; ++w) adj[tid * 8 + w] = 0u;   // 512*16 words / 1024 thr
    __syncthreads();

    // balanced half-pair enumeration, 2 threads per row
    {
        int row = tid >> 1;
        int h   = tid & 1;
        float4 mb = sbox[row];
        float  ar = sar[row];
        int kmax = (row < 256) ? 256 : 255;
        int k0 = h ? 129 : 1;
        int k1 = h ? kmax : 128;
        for (int k = k0; k <= k1; ++k) {
            int j = (row + k) & 511;
            float4 bj = sbox[j];
            float  aj = sar[j];
            float ix1 = fmaxf(mb.x, bj.x);
            float iy1 = fmaxf(mb.y, bj.y);
            float ix2 = fminf(mb.z, bj.z);
            float iy2 = fminf(mb.w, bj.w);
            float iw  = fmaxf(__fsub_rn(ix2, ix1), 0.f);
            float ih  = fmaxf(__fsub_rn(iy2, iy1), 0.f);
            float inter = __fmul_rn(iw, ih);
            float uniP  = __fadd_rn(__fsub_rn(__fadd_rn(ar, aj), inter), 1e-7f);
            float t2   = __fmul_rn(0.5f, uniP);
            float diff = __fsub_rn(inter, t2);
            bool hit;
            if (fabsf(diff) <= __fmul_rn(1e-6f, t2)) {
                float iou = __fdiv_rn(inter, uniP);   // exact decision in band
                hit = (iou >= NMS_THRESH);
            } else {
                hit = (diff > 0.f);
            }
            if (hit) {
                atomicOr(&adj[row * 16 + (j >> 5)], 1u << (j & 31));
                atomicOr(&adj[j * 16 + (row >> 5)], 1u << (row & 31));
            }
        }
    }
    __syncthreads();

    // serial greedy on warp 0 with one-ahead adjacency prefetch
    if (tid < 32) {
        int lane = tid;
        unsigned avail   = (lane < 16) ? s_validw[lane]     : 0u;
        unsigned nextadj = (lane < 16) ? adj[0 * 16 + lane] : 0u;
        for (int i = 0; i < TOPK; ++i) {
            unsigned myadj = nextadj;
            nextadj = (lane < 16 && i + 1 < 512) ? adj[(i + 1) * 16 + lane] : 0u;
            unsigned aw = __shfl_sync(0xFFFFFFFFu, avail, i >> 5);
            bool keep_i = (aw >> (i & 31)) & 1u;
            if (lane == 0) skeep[i] = keep_i ? 1 : 0;
            if (keep_i) avail &= ~myadj;
        }
    }
    __syncthreads();

    // outputs: [boxes (B*500*4)] [scores] [labels] [keep]
    if (r < TOPK) {
        bool kp = skeep[r] != 0;
        int row = b * TOPK + r;
        float* ob = out + row * 4;
        ob[0] = kp ? bb.x : 0.f;
        ob[1] = kp ? bb.y : 0.f;
        ob[2] = kp ? bb.z : 0.f;
        ob[3] = kp ? bb.w : 0.f;
        const int SBASE = B * TOPK * 4;
        const int LBASE = SBASE + B * TOPK;
        const int KBASE = LBASE + B * TOPK;
        out[SBASE + row] = kp ? sc : 0.f;
        out[LBASE + row] = (float)lab;
        out[KBASE + row] = kp ? 1.f : 0.f;
    }
}

// --------------------------------------------------------------- launch ----
extern "C" void kernel_launch(void* const* d_in, const int* in_sizes, int n_in,
                              void* d_out, int out_size)
{
    const float* cls_p3 = (const float*)d_in[0];
    const float* reg_p3 = (const float*)d_in[1];
    const float* obj_p3 = (const float*)d_in[2];
    const float* cls_p4 = (const float*)d_in[3];
    const float* reg_p4 = (const float*)d_in[4];
    const float* obj_p4 = (const float*)d_in[5];
    const float* cls_p5 = (const float*)d_in[6];
    const float* reg_p5 = (const float*)d_in[7];
    const float* obj_p5 = (const float*)d_in[8];
    float* out = (float*)d_out;

    void* p_cnt = nullptr;  void* p_hist = nullptr;
    cudaGetSymbolAddress(&p_cnt,  g_cnt);
    cudaGetSymbolAddress(&p_hist, g_hist);
    cudaMemsetAsync(p_cnt,  0, B * sizeof(int), 0);
    cudaMemsetAsync(p_hist, 0, B * NBIN * sizeof(int), 0);

    dim3 sgrid(17, B);
    scan_kernel<<<sgrid, 512>>>(cls_p3, obj_p3, cls_p4, obj_p4, cls_p5, obj_p5);
    select_nms_kernel<<<B, 1024>>>(cls_p3, reg_p3, obj_p3,
                                   cls_p4, reg_p4, obj_p4,
                                   cls_p5, reg_p5, obj_p5, out);
}

// round 12
// speedup vs baseline: 4.9718x; 1.0273x over previous
#include <cuda_runtime.h>
#include <cuda_bf16.h>
#include <math.h>

// Problem constants
#define B 64
#define NA 33600            // 160*160 + 80*80 + 40*40
#define TOPK 500
#define CAND 1024           // candidate sort size
#define NBIN 1024           // linear histogram bins over (0.3, 1.0]
#define SCORE_THRESH 0.3f
#define NMS_THRESH 0.5f
#define CLASS_OFFSET 10000.0f

#define P3_END 25600
#define P4_END 32000

typedef unsigned long long ull;

// ---------------- scratch (static device allocations; no runtime alloc) ----
__device__ float    g_scores[B * NA];       // only the pathological fallback
__device__ ull      g_cand[B * NA];         // per-batch approx candidate keys
__device__ int      g_cnt[B];
__device__ int      g_hist[B][NBIN];
// select -> adjacency/greedy handoff (512 slots per batch)
__device__ ull      g_keys [B * 512];       // sorted keys
__device__ float4   g_bboxg[B * 512];       // raw decoded boxes
__device__ float4   g_oboxg[B * 512];       // class-offset boxes
__device__ float    g_areag[B * 512];
__device__ int      g_labg [B * 512];
__device__ unsigned g_validwg[B * 16];
__device__ unsigned g_adj  [B * 512 * 16];  // IoU>=0.5 bitmatrix (memset 0)

// ------------------------------------------------------------ exp/sigmoid --
// Correctly-rounded float exp via double exp (matches XLA:CPU expf).
// Verified bit-compatible in R4-R10 — DO NOT change.
__device__ __forceinline__ float exp_cr(float x) {
    return (float)exp((double)x);
}
__device__ __forceinline__ float sig_e(float x) {
    float e = exp_cr(-x);
    return __fdiv_rn(1.0f, __fadd_rn(1.0f, e));
}
// fast sigmoid for the approximate path (product abs err < ~3e-6)
__device__ __forceinline__ float sig_fast(float x) {
    return __fdividef(1.0f, 1.0f + __expf(-x));
}

__device__ __forceinline__ unsigned int ordered_float(float f) {
    unsigned int u = __float_as_uint(f);
    return (u & 0x80000000u) ? ~u : (u | 0x80000000u);
}
__device__ __forceinline__ float inv_ordered(unsigned int u) {
    return __uint_as_float((u & 0x80000000u) ? (u ^ 0x80000000u) : ~u);
}
__device__ __forceinline__ int bin_of(float s) {
    int q = (int)(__fmul_rn(__fsub_rn(s, 0.3f), 1462.857f));
    if (q < 0) q = 0;
    return (q > NBIN - 1) ? (NBIN - 1) : q;
}

__device__ __forceinline__ void level_of(int idx, int& HW, int& W, float& stride, int& p, int& lvl) {
    if (idx < P3_END)      { HW = 25600; W = 160; stride = 8.f;  p = idx;          lvl = 0; }
    else if (idx < P4_END) { HW = 6400;  W = 80;  stride = 16.f; p = idx - P3_END; lvl = 1; }
    else                   { HW = 1600;  W = 40;  stride = 32.f; p = idx - P4_END; lvl = 2; }
}

// =================== kernel 1: highly-parallel approx scan =================
__global__ __launch_bounds__(512)
void scan_kernel(const float* __restrict__ cls3,
                 const float* __restrict__ obj3,
                 const float* __restrict__ cls4,
                 const float* __restrict__ obj4,
                 const float* __restrict__ cls5,
                 const float* __restrict__ obj5)
{
    __shared__ int   s_idx[2048];
    __shared__ float s_ap[2048];
    __shared__ int   s_hist[NBIN];
    __shared__ int   s_n, s_base;

    int b   = blockIdx.y;
    int tid = threadIdx.x;

    for (int d = tid; d < NBIN; d += 512) s_hist[d] = 0;
    if (tid == 0) s_n = 0;
    __syncthreads();

    int t = blockIdx.x * 512 + tid;
    int a = t * 4;
    if (a < NA) {
        const float* cls; const float* obj; int HW, p;
        if (a < P3_END)      { cls = cls3; obj = obj3; HW = 25600; p = a; }
        else if (a < P4_END) { cls = cls4; obj = obj4; HW = 6400;  p = a - P3_END; }
        else                 { cls = cls5; obj = obj5; HW = 1600;  p = a - P4_END; }

        float4 o4  = *(const float4*)(obj + b * HW + p);
        float4 c04 = *(const float4*)(cls + (b * 2 + 0) * HW + p);
        float4 c14 = *(const float4*)(cls + (b * 2 + 1) * HW + p);
        float oo[4]  = {o4.x, o4.y, o4.z, o4.w};
        float cc0[4] = {c04.x, c04.y, c04.z, c04.w};
        float cc1[4] = {c14.x, c14.y, c14.z, c14.w};

        #pragma unroll
        for (int j = 0; j < 4; ++j) {
            float cm = fmaxf(cc0[j], cc1[j]);
            float v  = sig_fast(oo[j]) * sig_fast(cm);
            if (v >= 0.29999f) {
                int pos = atomicAdd(&s_n, 1);
                s_idx[pos] = a + j; s_ap[pos] = v;
                atomicAdd(&s_hist[bin_of(v)], 1);
            }
        }
    }
    __syncthreads();

    if (tid == 0 && s_n) s_base = atomicAdd(&g_cnt[b], s_n);
    __syncthreads();

    int n = s_n;
    for (int i = tid; i < n; i += 512) {
        g_cand[b * NA + s_base + i] =
            ((ull)ordered_float(s_ap[i]) << 32) |
            (unsigned int)(~(unsigned int)s_idx[i]);
    }
    for (int d = tid; d < NBIN; d += 512) {
        int h = s_hist[d];
        if (h) atomicAdd(&g_hist[b][d], h);
    }
}

// =================== kernel 2: select (exact top-k) + box decode ===========
__global__ __launch_bounds__(1024, 1)
void select_kernel(const float* __restrict__ cls3,
                   const float* __restrict__ reg3,
                   const float* __restrict__ obj3,
                   const float* __restrict__ cls4,
                   const float* __restrict__ reg4,
                   const float* __restrict__ obj4,
                   const float* __restrict__ cls5,
                   const float* __restrict__ reg5,
                   const float* __restrict__ obj5)
{
    __shared__ __align__(16) unsigned char smem_raw[16384];
    int* hist = (int*)smem_raw;               // [0,4K)
    int* cidx = (int*)(smem_raw + 4096);      // [4K,8K)
    ull* ckey = (ull*)(smem_raw + 8192);      // [8K,16K)

    __shared__ int  coarse[NBIN / 4];
    __shared__ int  s_qp, s_cnt, s_nvalid, s_fallback;
    __shared__ ull  s_prefix;
    __shared__ int  s_k;
    __shared__ unsigned int s_vbm[32];
    __shared__ int  s_wpre[33];

    int b   = blockIdx.x;
    int tid = threadIdx.x;
    const int NT = 1024;
    int cnt_all = g_cnt[b];

    const float* CLS[3] = {cls3, cls4, cls5};
    const float* REG[3] = {reg3, reg4, reg5};
    const float* OBJ[3] = {obj3, obj4, obj5};

    if (tid == 0) { s_cnt = 0; s_nvalid = 0; s_fallback = 0; }
    if (tid < 32) s_vbm[tid] = 0u;
    __syncthreads();

    const ull* cl = g_cand + b * NA;

    if (cnt_all <= CAND) {
        for (int i = tid; i < cnt_all; i += NT)
            cidx[i] = (int)(~(unsigned int)cl[i]);
        if (tid == 0) s_cnt = cnt_all;
        __syncthreads();
    } else {
        for (int d = tid; d < NBIN; d += NT) hist[d] = g_hist[b][d];
        __syncthreads();
        if (tid < NBIN / 4)
            coarse[tid] = hist[4 * tid] + hist[4 * tid + 1] + hist[4 * tid + 2] + hist[4 * tid + 3];
        __syncthreads();
        if (tid == 0) {
            int cum = 0, qp = 0;
            for (int g = NBIN / 4 - 1; g >= 0; --g) {
                if (cum + coarse[g] >= TOPK) {
                    for (int d = 4 * g + 3; d >= 4 * g; --d) {
                        if (cum + hist[d] >= TOPK) { qp = d; break; }
                        cum += hist[d];
                    }
                    break;
                }
                cum += coarse[g];
            }
            s_qp = (qp > 0) ? qp - 1 : 0;
        }
        __syncthreads();
        int qp = s_qp;
        for (int i = tid; i < cnt_all; i += NT) {
            ull key = cl[i];
            float s = inv_ordered((unsigned int)(key >> 32));
            if (bin_of(s) >= qp) {
                int pos = atomicAdd(&s_cnt, 1);
                if (pos < CAND) cidx[pos] = (int)(~(unsigned int)key);
                else            s_fallback = 1;
            }
        }
        __syncthreads();
    }

    if (!s_fallback) {
        int m = s_cnt; if (m > CAND) m = CAND;
        for (int it = tid; it < m; it += NT) {
            int idx = cidx[it];
            int HW, W, p, lvl; float stride;
            level_of(idx, HW, W, stride, p, lvl);
            const float* cls = CLS[lvl];
            const float* obj = OBJ[lvl];
            float o  = obj[b * HW + p];
            float c0 = cls[(b * 2 + 0) * HW + p];
            float c1 = cls[(b * 2 + 1) * HW + p];
            float cmax = fmaxf(c0, c1);
            float smax = __fmul_rn(sig_e(o), sig_e(cmax));  // == max(s0,s1)
            ull key = 0ull;
            if (smax > SCORE_THRESH) {
                key = ((ull)ordered_float(smax) << 32) |
                      (unsigned int)(~(unsigned int)idx);
                atomicAdd(&s_nvalid, 1);
                if ((unsigned int)idx < 1024u)
                    atomicOr(&s_vbm[idx >> 5], 1u << (idx & 31));
            }
            ckey[it] = key;
        }
        __syncthreads();

        if (s_nvalid < TOPK) {
            int M = TOPK - s_nvalid;
            if (cnt_all <= CAND && s_cnt + M <= CAND) {
                if (tid == 0) {
                    int acc = 0;
                    for (int w = 0; w < 32; ++w) {
                        s_wpre[w] = acc;
                        acc += 32 - __popc(s_vbm[w]);
                    }
                    s_wpre[32] = acc;
                }
                __syncthreads();
                int base2 = s_cnt;
                {
                    int i = tid;
                    unsigned int bmw = s_vbm[i >> 5];
                    bool invalid = !((bmw >> (i & 31)) & 1u);
                    if (invalid) {
                        int rank = s_wpre[i >> 5] +
                                   __popc(~bmw & ((1u << (i & 31)) - 1u));
                        if (rank < M) {
                            ckey[base2 + rank] =
                                ((ull)ordered_float(-1.0f) << 32) |
                                (unsigned int)(~(unsigned int)i);
                        }
                    }
                }
                __syncthreads();
                if (tid == 0) s_cnt = base2 + M;
                __syncthreads();
            } else {
                s_fallback = 1;
            }
        }
    }
    __syncthreads();

    // pathological full-exact fallback (correct, slow, unexpected)
    if (s_fallback) {
        float* sc = g_scores + b * NA;
        for (int i = tid; i < NA; i += NT) {
            int HW, W, p, lvl; float stride;
            level_of(i, HW, W, stride, p, lvl);
            const float* cls = CLS[lvl];
            const float* obj = OBJ[lvl];
            float o  = obj[b * HW + p];
            float c0 = cls[(b * 2 + 0) * HW + p];
            float c1 = cls[(b * 2 + 1) * HW + p];
            float smax = __fmul_rn(sig_e(o), sig_e(fmaxf(c0, c1)));
            sc[i] = (smax > SCORE_THRESH) ? smax : -1.0f;
        }
        if (tid == 0) { s_prefix = 0ull; s_k = TOPK; s_cnt = 0; }
        __syncthreads();
        for (int pp = 7; pp >= 0; --pp) {
            for (int d = tid; d < 256; d += NT) hist[d] = 0;
            __syncthreads();
            ull pref = s_prefix;
            int sh = (pp + 1) * 8;
            for (int i = tid; i < NA; i += NT) {
                ull key = ((ull)ordered_float(sc[i]) << 32) |
                          (unsigned int)(~(unsigned int)i);
                bool match = (pp == 7) || ((key >> sh) == (pref >> sh));
                if (match) atomicAdd(&hist[(unsigned int)(key >> (pp * 8)) & 0xFFu], 1);
            }
            __syncthreads();
            if (tid == 0) {
                int k = s_k;
                for (int d = 255; d >= 0; --d) {
                    int c = hist[d];
                    if (k <= c) { s_prefix = pref | ((ull)d << (pp * 8)); break; }
                    k -= c;
                }
                s_k = k;
            }
            __syncthreads();
        }
        ull pivot = s_prefix;
        for (int i = tid; i < NA; i += NT) {
            ull key = ((ull)ordered_float(sc[i]) << 32) |
                      (unsigned int)(~(unsigned int)i);
            if (key >= pivot) {
                int pos = atomicAdd(&s_cnt, 1);
                if (pos < CAND) ckey[pos] = key;
            }
        }
        __syncthreads();
    }

    // pad + bitonic sort (descending), 1024 elems / 1024 threads
    int cnt = s_cnt; if (cnt > CAND) cnt = CAND;
    if (tid >= cnt) ckey[tid] = 0ull;
    __syncthreads();

    for (int k = 2; k <= CAND; k <<= 1) {
        for (int j = k >> 1; j > 0; j >>= 1) {
            int i = tid;
            int ixj = i ^ j;
            if (ixj > i) {
                bool desc = ((i & k) == 0);
                ull ka = ckey[i], kb = ckey[ixj];
                if (desc ? (ka < kb) : (ka > kb)) { ckey[i] = kb; ckey[ixj] = ka; }
            }
            __syncthreads();
        }
    }

    // ---- decode boxes + labels for top-512 slots, store handoff buffers ---
    int r = tid;
    ull myk = (r < 512) ? ckey[r] : 0ull;
    bool validf = false;

    if (r < TOPK) {
        int idx = (int)(~(unsigned int)myk);
        float sc = inv_ordered((unsigned int)(myk >> 32));
        if ((unsigned int)idx >= (unsigned int)NA) idx = 0;   // defensive

        int HW, W, p, lvl; float stride;
        level_of(idx, HW, W, stride, p, lvl);
        const float* reg = REG[lvl];
        const float* cls = CLS[lvl];
        const float* obj = OBJ[lvl];
        int y = p / W;
        int x = p - y * W;

        float dx = reg[(b * 4 + 0) * HW + p];
        float dy = reg[(b * 4 + 1) * HW + p];
        float dw = reg[(b * 4 + 2) * HW + p];
        float dh = reg[(b * 4 + 3) * HW + p];
        float cx = __fmul_rn(__fadd_rn((float)x, sig_e(dx)), stride);
        float cy = __fmul_rn(__fadd_rn((float)y, sig_e(dy)), stride);
        float w  = __fmul_rn(exp_cr(dw), stride);
        float h  = __fmul_rn(exp_cr(dh), stride);
        float wh = __fdiv_rn(w, 2.0f);
        float hh = __fdiv_rn(h, 2.0f);
        float4 bb;
        bb.x = __fsub_rn(cx, wh);
        bb.y = __fsub_rn(cy, hh);
        bb.z = __fadd_rn(cx, wh);
        bb.w = __fadd_rn(cy, hh);

        float c0 = cls[(b * 2 + 0) * HW + p];
        float c1 = cls[(b * 2 + 1) * HW + p];
        int lab = 0;
        if (c1 > c0) {
            if (__fsub_rn(c1, c0) < 1e-3f) {
                float o   = obj[b * HW + p];
                float so2 = sig_e(o);
                float s0  = __fmul_rn(so2, sig_e(c0));
                float s1  = __fmul_rn(so2, sig_e(c1));
                lab = (s1 > s0) ? 1 : 0;
            } else {
                lab = 1;
            }
        }

        float off = __fmul_rn((float)lab, CLASS_OFFSET);
        float x1 = __fadd_rn(bb.x, off);
        float y1 = __fadd_rn(bb.y, off);
        float x2 = __fadd_rn(bb.z, off);
        float y2 = __fadd_rn(bb.w, off);

        int gi = b * 512 + r;
        g_bboxg[gi] = bb;
        g_oboxg[gi] = make_float4(x1, y1, x2, y2);
        g_areag[gi] = __fmul_rn(__fsub_rn(x2, x1), __fsub_rn(y2, y1));
        g_labg [gi] = lab;
        g_keys [gi] = myk;
        validf = (sc > SCORE_THRESH);
    } else if (r < 512) {
        int gi = b * 512 + r;
        g_bboxg[gi] = make_float4(0.f, 0.f, 0.f, 0.f);
        g_oboxg[gi] = make_float4(0.f, 0.f, 0.f, 0.f);
        g_areag[gi] = 0.f;
        g_labg [gi] = 0;
        g_keys [gi] = myk;
    }

    unsigned vb = __ballot_sync(0xFFFFFFFFu, validf);
    if (r < 512 && (r & 31) == 0) g_validwg[b * 16 + (r >> 5)] = vb;
}

// =================== kernel 3: adjacency (2 blocks per batch) ==============
__global__ __launch_bounds__(512)
void adj_kernel()
{
    __shared__ float4 sobox[512];
    __shared__ float  sar[512];

    int b   = blockIdx.y;
    int h   = blockIdx.x;       // 0 or 1: distance-range half
    int r   = threadIdx.x;

    sobox[r] = g_oboxg[b * 512 + r];
    sar[r]   = g_areag[b * 512 + r];
    __syncthreads();

    unsigned* adjb = g_adj + b * 512 * 16;
    float4 mb = sobox[r];
    float  ar = sar[r];
    int kmax = (r < 256) ? 256 : 255;
    int k0 = (h == 0) ? 1   : 129;
    int k1 = (h == 0) ? 128 : kmax;
    for (int k = k0; k <= k1; ++k) {
        int j = (r + k) & 511;
        float4 bj = sobox[j];
        float  aj = sar[j];
        float ix1 = fmaxf(mb.x, bj.x);
        float iy1 = fmaxf(mb.y, bj.y);
        float ix2 = fminf(mb.z, bj.z);
        float iy2 = fminf(mb.w, bj.w);
        float iw  = fmaxf(__fsub_rn(ix2, ix1), 0.f);
        float ih  = fmaxf(__fsub_rn(iy2, iy1), 0.f);
        float inter = __fmul_rn(iw, ih);
        float uniP  = __fadd_rn(__fsub_rn(__fadd_rn(ar, aj), inter), 1e-7f);
        float t2   = __fmul_rn(0.5f, uniP);
        float diff = __fsub_rn(inter, t2);
        bool hit;
        if (fabsf(diff) <= __fmul_rn(1e-6f, t2)) {
            float iou = __fdiv_rn(inter, uniP);   // exact decision in guard band
            hit = (iou >= NMS_THRESH);
        } else {
            hit = (diff > 0.f);
        }
        if (hit) {
            atomicOr(&adjb[r * 16 + (j >> 5)], 1u << (j & 31));
            atomicOr(&adjb[j * 16 + (r >> 5)], 1u << (r & 31));
        }
    }
}

// =================== kernel 4: greedy NMS + outputs ========================
__global__ __launch_bounds__(512, 1)
void greedy_out_kernel(float* __restrict__ out)
{
    __shared__ unsigned adj_s[512 * 16];
    __shared__ unsigned char skeep[512];

    int b   = blockIdx.x;
    int tid = threadIdx.x;

    const unsigned* adjb = g_adj + b * 512 * 16;
    #pragma unroll
    for (int i = 0; i < 16; ++i)
        adj_s[i * 512 + tid] = adjb[i * 512 + tid];
    __syncthreads();

    if (tid < 32) {
        int lane = tid;
        unsigned avail   = (lane < 16) ? g_validwg[b * 16 + lane] : 0u;
        unsigned nextadj = (lane < 16) ? adj_s[0 * 16 + lane]     : 0u;
        for (int i = 0; i < TOPK; ++i) {
            unsigned myadj = nextadj;
            nextadj = (lane < 16 && i + 1 < 512) ? adj_s[(i + 1) * 16 + lane] : 0u;
            unsigned aw = __shfl_sync(0xFFFFFFFFu, avail, i >> 5);
            bool keep_i = (aw >> (i & 31)) & 1u;
            if (lane == 0) skeep[i] = keep_i ? 1 : 0;
            if (keep_i) avail &= ~myadj;
        }
    }
    __syncthreads();

    int r = tid;
    if (r < TOPK) {
        int gi = b * 512 + r;
        ull myk = g_keys[gi];
        float sc = inv_ordered((unsigned int)(myk >> 32));
        float4 bb = g_bboxg[gi];
        int lab = g_labg[gi];
        bool kp = skeep[r] != 0;
        int row = b * TOPK + r;
        float* ob = out + row * 4;
        ob[0] = kp ? bb.x : 0.f;
        ob[1] = kp ? bb.y : 0.f;
        ob[2] = kp ? bb.z : 0.f;
        ob[3] = kp ? bb.w : 0.f;
        const int SBASE = B * TOPK * 4;
        const int LBASE = SBASE + B * TOPK;
        const int KBASE = LBASE + B * TOPK;
        out[SBASE + row] = kp ? sc : 0.f;
        out[LBASE + row] = (float)lab;
        out[KBASE + row] = kp ? 1.f : 0.f;
    }
}

// --------------------------------------------------------------- launch ----
extern "C" void kernel_launch(void* const* d_in, const int* in_sizes, int n_in,
                              void* d_out, int out_size)
{
    const float* cls_p3 = (const float*)d_in[0];
    const float* reg_p3 = (const float*)d_in[1];
    const float* obj_p3 = (const float*)d_in[2];
    const float* cls_p4 = (const float*)d_in[3];
    const float* reg_p4 = (const float*)d_in[4];
    const float* obj_p4 = (const float*)d_in[5];
    const float* cls_p5 = (const float*)d_in[6];
    const float* reg_p5 = (const float*)d_in[7];
    const float* obj_p5 = (const float*)d_in[8];
    float* out = (float*)d_out;

    void* p_cnt = nullptr; void* p_hist = nullptr; void* p_adj = nullptr;
    cudaGetSymbolAddress(&p_cnt,  g_cnt);
    cudaGetSymbolAddress(&p_hist, g_hist);
    cudaGetSymbolAddress(&p_adj,  g_adj);
    cudaMemsetAsync(p_cnt,  0, B * sizeof(int), 0);
    cudaMemsetAsync(p_hist, 0, B * NBIN * sizeof(int), 0);
    cudaMemsetAsync(p_adj,  0, B * 512 * 16 * sizeof(unsigned), 0);

    dim3 sgrid(17, B);
    scan_kernel<<<sgrid, 512>>>(cls_p3, obj_p3, cls_p4, obj_p4, cls_p5, obj_p5);
    select_kernel<<<B, 1024>>>(cls_p3, reg_p3, obj_p3,
                               cls_p4, reg_p4, obj_p4,
                               cls_p5, reg_p5, obj_p5);
    dim3 agrid(2, B);
    adj_kernel<<<agrid, 512>>>();
    greedy_out_kernel<<<B, 512>>>(out);
}

// round 13
// speedup vs baseline: 5.4238x; 1.0909x over previous
#include <cuda_runtime.h>
#include <cuda_bf16.h>
#include <math.h>

// Problem constants
#define B 64
#define NA 33600            // 160*160 + 80*80 + 40*40
#define TOPK 500
#define CAND 1024           // candidate sort size
#define NBIN 1024           // linear histogram bins over (0.3, 1.0]
#define SCORE_THRESH 0.3f
#define NMS_THRESH 0.5f
#define CLASS_OFFSET 10000.0f

#define P3_END 25600
#define P4_END 32000

typedef unsigned long long ull;

// ---------------- scratch (static device allocations; no runtime alloc) ----
__device__ float    g_scores[B * NA];       // only the pathological fallback
__device__ ull      g_cand[B * NA];         // per-batch approx candidate keys
__device__ int      g_cnt[B];
__device__ int      g_hist[B][NBIN];
// select -> adjacency/greedy handoff (512 slots per batch)
__device__ ull      g_keys [B * 512];       // sorted keys
__device__ float4   g_bboxg[B * 512];       // raw decoded boxes
__device__ float4   g_oboxg[B * 512];       // class-offset boxes
__device__ float    g_areag[B * 512];
__device__ int      g_labg [B * 512];
__device__ unsigned g_validwg[B * 16];
__device__ unsigned g_adj  [B * 512 * 16];  // IoU>=0.5 bitmatrix (memset 0)

// ------------------------------------------------------------ exp/sigmoid --
// Correctly-rounded float exp via double exp (matches XLA:CPU expf).
// Verified bit-compatible in R4-R12 — DO NOT change.
__device__ __forceinline__ float exp_cr(float x) {
    return (float)exp((double)x);
}
__device__ __forceinline__ float sig_e(float x) {
    float e = exp_cr(-x);
    return __fdiv_rn(1.0f, __fadd_rn(1.0f, e));
}
// fast sigmoid for the approximate path (product abs err < ~3e-6)
__device__ __forceinline__ float sig_fast(float x) {
    return __fdividef(1.0f, 1.0f + __expf(-x));
}

__device__ __forceinline__ unsigned int ordered_float(float f) {
    unsigned int u = __float_as_uint(f);
    return (u & 0x80000000u) ? ~u : (u | 0x80000000u);
}
__device__ __forceinline__ float inv_ordered(unsigned int u) {
    return __uint_as_float((u & 0x80000000u) ? (u ^ 0x80000000u) : ~u);
}
__device__ __forceinline__ int bin_of(float s) {
    int q = (int)(__fmul_rn(__fsub_rn(s, 0.3f), 1462.857f));
    if (q < 0) q = 0;
    return (q > NBIN - 1) ? (NBIN - 1) : q;
}

__device__ __forceinline__ void level_of(int idx, int& HW, int& W, float& stride, int& p, int& lvl) {
    if (idx < P3_END)      { HW = 25600; W = 160; stride = 8.f;  p = idx;          lvl = 0; }
    else if (idx < P4_END) { HW = 6400;  W = 80;  stride = 16.f; p = idx - P3_END; lvl = 1; }
    else                   { HW = 1600;  W = 40;  stride = 32.f; p = idx - P4_END; lvl = 2; }
}

// =================== kernel 1: highly-parallel approx scan =================
__global__ __launch_bounds__(512)
void scan_kernel(const float* __restrict__ cls3,
                 const float* __restrict__ obj3,
                 const float* __restrict__ cls4,
                 const float* __restrict__ obj4,
                 const float* __restrict__ cls5,
                 const float* __restrict__ obj5)
{
    __shared__ int   s_idx[2048];
    __shared__ float s_ap[2048];
    __shared__ int   s_hist[NBIN];
    __shared__ int   s_n, s_base;

    int b   = blockIdx.y;
    int tid = threadIdx.x;

    for (int d = tid; d < NBIN; d += 512) s_hist[d] = 0;
    if (tid == 0) s_n = 0;
    __syncthreads();

    int t = blockIdx.x * 512 + tid;
    int a = t * 4;
    if (a < NA) {
        const float* cls; const float* obj; int HW, p;
        if (a < P3_END)      { cls = cls3; obj = obj3; HW = 25600; p = a; }
        else if (a < P4_END) { cls = cls4; obj = obj4; HW = 6400;  p = a - P3_END; }
        else                 { cls = cls5; obj = obj5; HW = 1600;  p = a - P4_END; }

        float4 o4  = *(const float4*)(obj + b * HW + p);
        float4 c04 = *(const float4*)(cls + (b * 2 + 0) * HW + p);
        float4 c14 = *(const float4*)(cls + (b * 2 + 1) * HW + p);
        float oo[4]  = {o4.x, o4.y, o4.z, o4.w};
        float cc0[4] = {c04.x, c04.y, c04.z, c04.w};
        float cc1[4] = {c14.x, c14.y, c14.z, c14.w};

        #pragma unroll
        for (int j = 0; j < 4; ++j) {
            float cm = fmaxf(cc0[j], cc1[j]);
            float v  = sig_fast(oo[j]) * sig_fast(cm);
            if (v >= 0.29999f) {
                int pos = atomicAdd(&s_n, 1);
                s_idx[pos] = a + j; s_ap[pos] = v;
                atomicAdd(&s_hist[bin_of(v)], 1);
            }
        }
    }
    __syncthreads();

    if (tid == 0 && s_n) s_base = atomicAdd(&g_cnt[b], s_n);
    __syncthreads();

    int n = s_n;
    for (int i = tid; i < n; i += 512) {
        g_cand[b * NA + s_base + i] =
            ((ull)ordered_float(s_ap[i]) << 32) |
            (unsigned int)(~(unsigned int)s_idx[i]);
    }
    for (int d = tid; d < NBIN; d += 512) {
        int h = s_hist[d];
        if (h) atomicAdd(&g_hist[b][d], h);
    }
}

// =================== kernel 2: select (exact top-k) + box decode ===========
__global__ __launch_bounds__(1024, 1)
void select_kernel(const float* __restrict__ cls3,
                   const float* __restrict__ reg3,
                   const float* __restrict__ obj3,
                   const float* __restrict__ cls4,
                   const float* __restrict__ reg4,
                   const float* __restrict__ obj4,
                   const float* __restrict__ cls5,
                   const float* __restrict__ reg5,
                   const float* __restrict__ obj5)
{
    __shared__ __align__(16) unsigned char smem_raw[16384];
    int* hist = (int*)smem_raw;               // [0,4K)
    int* cidx = (int*)(smem_raw + 4096);      // [4K,8K)
    ull* ckey = (ull*)(smem_raw + 8192);      // [8K,16K)

    __shared__ int  coarse[NBIN / 4];
    __shared__ int  s_qp, s_cnt, s_nvalid, s_fallback;
    __shared__ ull  s_prefix;
    __shared__ int  s_k;
    __shared__ unsigned int s_vbm[32];
    __shared__ int  s_wpre[33];

    int b   = blockIdx.x;
    int tid = threadIdx.x;
    const int NT = 1024;
    int cnt_all = g_cnt[b];

    const float* CLS[3] = {cls3, cls4, cls5};
    const float* REG[3] = {reg3, reg4, reg5};
    const float* OBJ[3] = {obj3, obj4, obj5};

    if (tid == 0) { s_cnt = 0; s_nvalid = 0; s_fallback = 0; }
    if (tid < 32) s_vbm[tid] = 0u;
    __syncthreads();

    const ull* cl = g_cand + b * NA;

    if (cnt_all <= CAND) {
        for (int i = tid; i < cnt_all; i += NT)
            cidx[i] = (int)(~(unsigned int)cl[i]);
        if (tid == 0) s_cnt = cnt_all;
        __syncthreads();
    } else {
        for (int d = tid; d < NBIN; d += NT) hist[d] = g_hist[b][d];
        __syncthreads();
        if (tid < NBIN / 4)
            coarse[tid] = hist[4 * tid] + hist[4 * tid + 1] + hist[4 * tid + 2] + hist[4 * tid + 3];
        __syncthreads();
        if (tid == 0) {
            int cum = 0, qp = 0;
            for (int g = NBIN / 4 - 1; g >= 0; --g) {
                if (cum + coarse[g] >= TOPK) {
                    for (int d = 4 * g + 3; d >= 4 * g; --d) {
                        if (cum + hist[d] >= TOPK) { qp = d; break; }
                        cum += hist[d];
                    }
                    break;
                }
                cum += coarse[g];
            }
            s_qp = (qp > 0) ? qp - 1 : 0;
        }
        __syncthreads();
        int qp = s_qp;
        for (int i = tid; i < cnt_all; i += NT) {
            ull key = cl[i];
            float s = inv_ordered((unsigned int)(key >> 32));
            if (bin_of(s) >= qp) {
                int pos = atomicAdd(&s_cnt, 1);
                if (pos < CAND) cidx[pos] = (int)(~(unsigned int)key);
                else            s_fallback = 1;
            }
        }
        __syncthreads();
    }

    if (!s_fallback) {
        int m = s_cnt; if (m > CAND) m = CAND;
        for (int it = tid; it < m; it += NT) {
            int idx = cidx[it];
            int HW, W, p, lvl; float stride;
            level_of(idx, HW, W, stride, p, lvl);
            const float* cls = CLS[lvl];
            const float* obj = OBJ[lvl];
            float o  = obj[b * HW + p];
            float c0 = cls[(b * 2 + 0) * HW + p];
            float c1 = cls[(b * 2 + 1) * HW + p];
            float cmax = fmaxf(c0, c1);
            float smax = __fmul_rn(sig_e(o), sig_e(cmax));  // == max(s0,s1)
            ull key = 0ull;
            if (smax > SCORE_THRESH) {
                key = ((ull)ordered_float(smax) << 32) |
                      (unsigned int)(~(unsigned int)idx);
                atomicAdd(&s_nvalid, 1);
                if ((unsigned int)idx < 1024u)
                    atomicOr(&s_vbm[idx >> 5], 1u << (idx & 31));
            }
            ckey[it] = key;
        }
        __syncthreads();

        if (s_nvalid < TOPK) {
            int M = TOPK - s_nvalid;
            if (cnt_all <= CAND && s_cnt + M <= CAND) {
                if (tid == 0) {
                    int acc = 0;
                    for (int w = 0; w < 32; ++w) {
                        s_wpre[w] = acc;
                        acc += 32 - __popc(s_vbm[w]);
                    }
                    s_wpre[32] = acc;
                }
                __syncthreads();
                int base2 = s_cnt;
                {
                    int i = tid;
                    unsigned int bmw = s_vbm[i >> 5];
                    bool invalid = !((bmw >> (i & 31)) & 1u);
                    if (invalid) {
                        int rank = s_wpre[i >> 5] +
                                   __popc(~bmw & ((1u << (i & 31)) - 1u));
                        if (rank < M) {
                            ckey[base2 + rank] =
                                ((ull)ordered_float(-1.0f) << 32) |
                                (unsigned int)(~(unsigned int)i);
                        }
                    }
                }
                __syncthreads();
                if (tid == 0) s_cnt = base2 + M;
                __syncthreads();
            } else {
                s_fallback = 1;
            }
        }
    }
    __syncthreads();

    // pathological full-exact fallback (correct, slow, unexpected)
    if (s_fallback) {
        float* sc = g_scores + b * NA;
        for (int i = tid; i < NA; i += NT) {
            int HW, W, p, lvl; float stride;
            level_of(i, HW, W, stride, p, lvl);
            const float* cls = CLS[lvl];
            const float* obj = OBJ[lvl];
            float o  = obj[b * HW + p];
            float c0 = cls[(b * 2 + 0) * HW + p];
            float c1 = cls[(b * 2 + 1) * HW + p];
            float smax = __fmul_rn(sig_e(o), sig_e(fmaxf(c0, c1)));
            sc[i] = (smax > SCORE_THRESH) ? smax : -1.0f;
        }
        if (tid == 0) { s_prefix = 0ull; s_k = TOPK; s_cnt = 0; }
        __syncthreads();
        for (int pp = 7; pp >= 0; --pp) {
            for (int d = tid; d < 256; d += NT) hist[d] = 0;
            __syncthreads();
            ull pref = s_prefix;
            int sh = (pp + 1) * 8;
            for (int i = tid; i < NA; i += NT) {
                ull key = ((ull)ordered_float(sc[i]) << 32) |
                          (unsigned int)(~(unsigned int)i);
                bool match = (pp == 7) || ((key >> sh) == (pref >> sh));
                if (match) atomicAdd(&hist[(unsigned int)(key >> (pp * 8)) & 0xFFu], 1);
            }
            __syncthreads();
            if (tid == 0) {
                int k = s_k;
                for (int d = 255; d >= 0; --d) {
                    int c = hist[d];
                    if (k <= c) { s_prefix = pref | ((ull)d << (pp * 8)); break; }
                    k -= c;
                }
                s_k = k;
            }
            __syncthreads();
        }
        ull pivot = s_prefix;
        for (int i = tid; i < NA; i += NT) {
            ull key = ((ull)ordered_float(sc[i]) << 32) |
                      (unsigned int)(~(unsigned int)i);
            if (key >= pivot) {
                int pos = atomicAdd(&s_cnt, 1);
                if (pos < CAND) ckey[pos] = key;
            }
        }
        __syncthreads();
    }

    // pad + bitonic sort (descending), 1024 elems / 1024 threads
    int cnt = s_cnt; if (cnt > CAND) cnt = CAND;
    if (tid >= cnt) ckey[tid] = 0ull;
    __syncthreads();

    for (int k = 2; k <= CAND; k <<= 1) {
        for (int j = k >> 1; j > 0; j >>= 1) {
            int i = tid;
            int ixj = i ^ j;
            if (ixj > i) {
                bool desc = ((i & k) == 0);
                ull ka = ckey[i], kb = ckey[ixj];
                if (desc ? (ka < kb) : (ka > kb)) { ckey[i] = kb; ckey[ixj] = ka; }
            }
            __syncthreads();
        }
    }

    // ---- decode boxes + labels for top-512 slots, store handoff buffers ---
    int r = tid;
    ull myk = (r < 512) ? ckey[r] : 0ull;
    bool validf = false;

    if (r < TOPK) {
        int idx = (int)(~(unsigned int)myk);
        float sc = inv_ordered((unsigned int)(myk >> 32));
        if ((unsigned int)idx >= (unsigned int)NA) idx = 0;   // defensive

        int HW, W, p, lvl; float stride;
        level_of(idx, HW, W, stride, p, lvl);
        const float* reg = REG[lvl];
        const float* cls = CLS[lvl];
        const float* obj = OBJ[lvl];
        int y = p / W;
        int x = p - y * W;

        float dx = reg[(b * 4 + 0) * HW + p];
        float dy = reg[(b * 4 + 1) * HW + p];
        float dw = reg[(b * 4 + 2) * HW + p];
        float dh = reg[(b * 4 + 3) * HW + p];
        float cx = __fmul_rn(__fadd_rn((float)x, sig_e(dx)), stride);
        float cy = __fmul_rn(__fadd_rn((float)y, sig_e(dy)), stride);
        float w  = __fmul_rn(exp_cr(dw), stride);
        float h  = __fmul_rn(exp_cr(dh), stride);
        float wh = __fdiv_rn(w, 2.0f);
        float hh = __fdiv_rn(h, 2.0f);
        float4 bb;
        bb.x = __fsub_rn(cx, wh);
        bb.y = __fsub_rn(cy, hh);
        bb.z = __fadd_rn(cx, wh);
        bb.w = __fadd_rn(cy, hh);

        float c0 = cls[(b * 2 + 0) * HW + p];
        float c1 = cls[(b * 2 + 1) * HW + p];
        int lab = 0;
        if (c1 > c0) {
            if (__fsub_rn(c1, c0) < 1e-3f) {
                float o   = obj[b * HW + p];
                float so2 = sig_e(o);
                float s0  = __fmul_rn(so2, sig_e(c0));
                float s1  = __fmul_rn(so2, sig_e(c1));
                lab = (s1 > s0) ? 1 : 0;
            } else {
                lab = 1;
            }
        }

        float off = __fmul_rn((float)lab, CLASS_OFFSET);
        float x1 = __fadd_rn(bb.x, off);
        float y1 = __fadd_rn(bb.y, off);
        float x2 = __fadd_rn(bb.z, off);
        float y2 = __fadd_rn(bb.w, off);

        int gi = b * 512 + r;
        g_bboxg[gi] = bb;
        g_oboxg[gi] = make_float4(x1, y1, x2, y2);
        g_areag[gi] = __fmul_rn(__fsub_rn(x2, x1), __fsub_rn(y2, y1));
        g_labg [gi] = lab;
        g_keys [gi] = myk;
        validf = (sc > SCORE_THRESH);
    } else if (r < 512) {
        int gi = b * 512 + r;
        g_bboxg[gi] = make_float4(0.f, 0.f, 0.f, 0.f);
        g_oboxg[gi] = make_float4(0.f, 0.f, 0.f, 0.f);
        g_areag[gi] = 0.f;
        g_labg [gi] = 0;
        g_keys [gi] = myk;
    }

    unsigned vb = __ballot_sync(0xFFFFFFFFu, validf);
    if (r < 512 && (r & 31) == 0) g_validwg[b * 16 + (r >> 5)] = vb;
}

// =================== kernel 3: adjacency (2 blocks per batch) ==============
__global__ __launch_bounds__(512)
void adj_kernel()
{
    __shared__ float4 sobox[512];
    __shared__ float  sar[512];

    int b   = blockIdx.y;
    int h   = blockIdx.x;       // 0 or 1: distance-range half
    int r   = threadIdx.x;

    sobox[r] = g_oboxg[b * 512 + r];
    sar[r]   = g_areag[b * 512 + r];
    __syncthreads();

    unsigned* adjb = g_adj + b * 512 * 16;
    float4 mb = sobox[r];
    float  ar = sar[r];
    int kmax = (r < 256) ? 256 : 255;
    int k0 = (h == 0) ? 1   : 129;
    int k1 = (h == 0) ? 128 : kmax;
    for (int k = k0; k <= k1; ++k) {
        int j = (r + k) & 511;
        float4 bj = sobox[j];
        float  aj = sar[j];
        float ix1 = fmaxf(mb.x, bj.x);
        float iy1 = fmaxf(mb.y, bj.y);
        float ix2 = fminf(mb.z, bj.z);
        float iy2 = fminf(mb.w, bj.w);
        float iw  = fmaxf(__fsub_rn(ix2, ix1), 0.f);
        float ih  = fmaxf(__fsub_rn(iy2, iy1), 0.f);
        float inter = __fmul_rn(iw, ih);
        float uniP  = __fadd_rn(__fsub_rn(__fadd_rn(ar, aj), inter), 1e-7f);
        float t2   = __fmul_rn(0.5f, uniP);
        float diff = __fsub_rn(inter, t2);
        bool hit;
        if (fabsf(diff) <= __fmul_rn(1e-6f, t2)) {
            float iou = __fdiv_rn(inter, uniP);   // exact decision in guard band
            hit = (iou >= NMS_THRESH);
        } else {
            hit = (diff > 0.f);
        }
        if (hit) {
            atomicOr(&adjb[r * 16 + (j >> 5)], 1u << (j & 31));
            atomicOr(&adjb[j * 16 + (r >> 5)], 1u << (r & 31));
        }
    }
}

// =================== kernel 4: windowed greedy NMS + outputs ===============
__global__ __launch_bounds__(512, 1)
void greedy_out_kernel(float* __restrict__ out)
{
    __shared__ unsigned adj_s[512 * 16];
    __shared__ unsigned skeepw[16];

    int b   = blockIdx.x;
    int tid = threadIdx.x;

    const unsigned* adjb = g_adj + b * 512 * 16;
    #pragma unroll
    for (int i = 0; i < 16; ++i)
        adj_s[i * 512 + tid] = adjb[i * 512 + tid];
    __syncthreads();

    // windowed warp greedy: 16 windows of 32; lane w resolves window w locally
    // (adjacency has no self-bits, so within-window updates == reference order),
    // then one shfl broadcasts the keep mask and all lanes apply cross-window
    // suppression with independent pipelined LDS.
    if (tid < 32) {
        int lane = tid;
        unsigned avail = (lane < 16) ? g_validwg[b * 16 + lane] : 0u;
        #pragma unroll 1
        for (int w = 0; w < 16; ++w) {
            unsigned km = 0;
            if (lane == w) {
                unsigned aw = avail;
                unsigned col[32];
                #pragma unroll
                for (int b2 = 0; b2 < 32; ++b2)
                    col[b2] = adj_s[(w * 32 + b2) * 16 + w];
                #pragma unroll
                for (int b2 = 0; b2 < 32; ++b2) {
                    if ((aw >> b2) & 1u) {
                        km |= 1u << b2;
                        aw &= ~col[b2];
                    }
                }
            }
            km = __shfl_sync(0xFFFFFFFFu, km, w);
            if (lane < 16) {
                #pragma unroll
                for (int b2 = 0; b2 < 32; ++b2) {
                    if ((km >> b2) & 1u)
                        avail &= ~adj_s[(w * 32 + b2) * 16 + lane];
                }
            }
            if (lane == 0) skeepw[w] = km;
        }
    }
    __syncthreads();

    int r = tid;
    if (r < TOPK) {
        int gi = b * 512 + r;
        ull myk = g_keys[gi];
        float sc = inv_ordered((unsigned int)(myk >> 32));
        float4 bb = g_bboxg[gi];
        int lab = g_labg[gi];
        bool kp = (skeepw[r >> 5] >> (r & 31)) & 1u;
        int row = b * TOPK + r;
        float* ob = out + row * 4;
        ob[0] = kp ? bb.x : 0.f;
        ob[1] = kp ? bb.y : 0.f;
        ob[2] = kp ? bb.z : 0.f;
        ob[3] = kp ? bb.w : 0.f;
        const int SBASE = B * TOPK * 4;
        const int LBASE = SBASE + B * TOPK;
        const int KBASE = LBASE + B * TOPK;
        out[SBASE + row] = kp ? sc : 0.f;
        out[LBASE + row] = (float)lab;
        out[KBASE + row] = kp ? 1.f : 0.f;
    }
}

// --------------------------------------------------------------- launch ----
extern "C" void kernel_launch(void* const* d_in, const int* in_sizes, int n_in,
                              void* d_out, int out_size)
{
    const float* cls_p3 = (const float*)d_in[0];
    const float* reg_p3 = (const float*)d_in[1];
    const float* obj_p3 = (const float*)d_in[2];
    const float* cls_p4 = (const float*)d_in[3];
    const float* reg_p4 = (const float*)d_in[4];
    const float* obj_p4 = (const float*)d_in[5];
    const float* cls_p5 = (const float*)d_in[6];
    const float* reg_p5 = (const float*)d_in[7];
    const float* obj_p5 = (const float*)d_in[8];
    float* out = (float*)d_out;

    void* p_cnt = nullptr; void* p_hist = nullptr; void* p_adj = nullptr;
    cudaGetSymbolAddress(&p_cnt,  g_cnt);
    cudaGetSymbolAddress(&p_hist, g_hist);
    cudaGetSymbolAddress(&p_adj,  g_adj);
    cudaMemsetAsync(p_cnt,  0, B * sizeof(int), 0);
    cudaMemsetAsync(p_hist, 0, B * NBIN * sizeof(int), 0);
    cudaMemsetAsync(p_adj,  0, B * 512 * 16 * sizeof(unsigned), 0);

    dim3 sgrid(17, B);
    scan_kernel<<<sgrid, 512>>>(cls_p3, obj_p3, cls_p4, obj_p4, cls_p5, obj_p5);
    select_kernel<<<B, 1024>>>(cls_p3, reg_p3, obj_p3,
                               cls_p4, reg_p4, obj_p4,
                               cls_p5, reg_p5, obj_p5);
    dim3 agrid(2, B);
    adj_kernel<<<agrid, 512>>>();
    greedy_out_kernel<<<B, 512>>>(out);
}

// round 14
// speedup vs baseline: 5.5796x; 1.0287x over previous
#include <cuda_runtime.h>
#include <cuda_bf16.h>
#include <math.h>

// Problem constants
#define B 64
#define NA 33600            // 160*160 + 80*80 + 40*40
#define TOPK 500
#define CAND 1024           // candidate sort size
#define NBIN 1024           // linear histogram bins over (0.3, 1.0]
#define SCORE_THRESH 0.3f
#define NMS_THRESH 0.5f
#define CLASS_OFFSET 10000.0f

#define P3_END 25600
#define P4_END 32000

typedef unsigned long long ull;

// ---------------- scratch (static device allocations; no runtime alloc) ----
struct ZeroBlock {               // zeroed by ONE memset node per launch
    int cnt[B];
    int hist[B][NBIN];
};
__device__ ZeroBlock g_zs;
__device__ float g_scores[B * NA];      // only the pathological fallback
__device__ ull   g_cand[B * NA];        // per-batch approx candidate keys

// ------------------------------------------------------------ exp/sigmoid --
// Correctly-rounded float exp via double exp (matches XLA:CPU expf).
// Verified bit-compatible in R4-R13 — DO NOT change.
__device__ __forceinline__ float exp_cr(float x) {
    return (float)exp((double)x);
}
__device__ __forceinline__ float sig_e(float x) {
    float e = exp_cr(-x);
    return __fdiv_rn(1.0f, __fadd_rn(1.0f, e));
}
// fast sigmoid for the approximate path (product abs err < ~3e-6)
__device__ __forceinline__ float sig_fast(float x) {
    return __fdividef(1.0f, 1.0f + __expf(-x));
}

__device__ __forceinline__ unsigned int ordered_float(float f) {
    unsigned int u = __float_as_uint(f);
    return (u & 0x80000000u) ? ~u : (u | 0x80000000u);
}
__device__ __forceinline__ float inv_ordered(unsigned int u) {
    return __uint_as_float((u & 0x80000000u) ? (u ^ 0x80000000u) : ~u);
}
__device__ __forceinline__ int bin_of(float s) {
    int q = (int)(__fmul_rn(__fsub_rn(s, 0.3f), 1462.857f));
    if (q < 0) q = 0;
    return (q > NBIN - 1) ? (NBIN - 1) : q;
}

__device__ __forceinline__ void level_of(int idx, int& HW, int& W, float& stride, int& p, int& lvl) {
    if (idx < P3_END)      { HW = 25600; W = 160; stride = 8.f;  p = idx;          lvl = 0; }
    else if (idx < P4_END) { HW = 6400;  W = 80;  stride = 16.f; p = idx - P3_END; lvl = 1; }
    else                   { HW = 1600;  W = 40;  stride = 32.f; p = idx - P4_END; lvl = 2; }
}

// =================== kernel 1: highly-parallel approx scan =================
__global__ __launch_bounds__(512)
void scan_kernel(const float* __restrict__ cls3,
                 const float* __restrict__ obj3,
                 const float* __restrict__ cls4,
                 const float* __restrict__ obj4,
                 const float* __restrict__ cls5,
                 const float* __restrict__ obj5)
{
    __shared__ int   s_idx[2048];
    __shared__ float s_ap[2048];
    __shared__ int   s_hist[NBIN];
    __shared__ int   s_n, s_base;

    int b   = blockIdx.y;
    int tid = threadIdx.x;

    for (int d = tid; d < NBIN; d += 512) s_hist[d] = 0;
    if (tid == 0) s_n = 0;
    __syncthreads();

    int t = blockIdx.x * 512 + tid;
    int a = t * 4;
    if (a < NA) {
        const float* cls; const float* obj; int HW, p;
        if (a < P3_END)      { cls = cls3; obj = obj3; HW = 25600; p = a; }
        else if (a < P4_END) { cls = cls4; obj = obj4; HW = 6400;  p = a - P3_END; }
        else                 { cls = cls5; obj = obj5; HW = 1600;  p = a - P4_END; }

        float4 o4  = *(const float4*)(obj + b * HW + p);
        float4 c04 = *(const float4*)(cls + (b * 2 + 0) * HW + p);
        float4 c14 = *(const float4*)(cls + (b * 2 + 1) * HW + p);
        float oo[4]  = {o4.x, o4.y, o4.z, o4.w};
        float cc0[4] = {c04.x, c04.y, c04.z, c04.w};
        float cc1[4] = {c14.x, c14.y, c14.z, c14.w};

        #pragma unroll
        for (int j = 0; j < 4; ++j) {
            float cm = fmaxf(cc0[j], cc1[j]);
            float v  = sig_fast(oo[j]) * sig_fast(cm);
            if (v >= 0.29999f) {
                int pos = atomicAdd(&s_n, 1);
                s_idx[pos] = a + j; s_ap[pos] = v;
                atomicAdd(&s_hist[bin_of(v)], 1);
            }
        }
    }
    __syncthreads();

    if (tid == 0 && s_n) s_base = atomicAdd(&g_zs.cnt[b], s_n);
    __syncthreads();

    int n = s_n;
    for (int i = tid; i < n; i += 512) {
        g_cand[b * NA + s_base + i] =
            ((ull)ordered_float(s_ap[i]) << 32) |
            (unsigned int)(~(unsigned int)s_idx[i]);
    }
    for (int d = tid; d < NBIN; d += 512) {
        int h = s_hist[d];
        if (h) atomicAdd(&g_zs.hist[b][d], h);
    }
}

// ========== kernel 2: select (exact top-k) + adjacency + greedy + out ======
__global__ __launch_bounds__(1024, 1)
void select_nms_kernel(const float* __restrict__ cls3,
                       const float* __restrict__ reg3,
                       const float* __restrict__ obj3,
                       const float* __restrict__ cls4,
                       const float* __restrict__ reg4,
                       const float* __restrict__ obj4,
                       const float* __restrict__ cls5,
                       const float* __restrict__ reg5,
                       const float* __restrict__ obj5,
                       float* __restrict__ out)
{
    // shared union:
    //  select phase: hist[0,4K) cidx[4K,8K) ckey[8K,16K)
    //  NMS phase:    sbox[0,8K) sar[8K,10K) adj[10K,42K)
    __shared__ __align__(16) unsigned char smem_raw[43008];
    int*    hist = (int*)smem_raw;
    int*    cidx = (int*)(smem_raw + 4096);
    ull*    ckey = (ull*)(smem_raw + 8192);
    float4* sbox = (float4*)smem_raw;
    float*  sar  = (float*)(smem_raw + 8192);
    unsigned int* adj = (unsigned int*)(smem_raw + 10240);

    __shared__ int  coarse[NBIN / 4];
    __shared__ int  s_qp, s_cnt, s_nvalid, s_fallback;
    __shared__ ull  s_prefix;
    __shared__ int  s_k;
    __shared__ unsigned int s_validw[16];
    __shared__ unsigned int skeepw[16];
    __shared__ unsigned int s_vbm[32];
    __shared__ int  s_wpre[33];

    int b   = blockIdx.x;
    int tid = threadIdx.x;
    const int NT = 1024;
    int cnt_all = g_zs.cnt[b];

    const float* CLS[3] = {cls3, cls4, cls5};
    const float* REG[3] = {reg3, reg4, reg5};
    const float* OBJ[3] = {obj3, obj4, obj5};

    if (tid == 0) { s_cnt = 0; s_nvalid = 0; s_fallback = 0; }
    if (tid < 32) s_vbm[tid] = 0u;
    __syncthreads();

    const ull* cl = g_cand + b * NA;

    if (cnt_all <= CAND) {
        for (int i = tid; i < cnt_all; i += NT)
            cidx[i] = (int)(~(unsigned int)cl[i]);
        if (tid == 0) s_cnt = cnt_all;
        __syncthreads();
    } else {
        for (int d = tid; d < NBIN; d += NT) hist[d] = g_zs.hist[b][d];
        __syncthreads();
        if (tid < NBIN / 4)
            coarse[tid] = hist[4 * tid] + hist[4 * tid + 1] + hist[4 * tid + 2] + hist[4 * tid + 3];
        __syncthreads();
        if (tid == 0) {
            int cum = 0, qp = 0;
            for (int g = NBIN / 4 - 1; g >= 0; --g) {
                if (cum + coarse[g] >= TOPK) {
                    for (int d = 4 * g + 3; d >= 4 * g; --d) {
                        if (cum + hist[d] >= TOPK) { qp = d; break; }
                        cum += hist[d];
                    }
                    break;
                }
                cum += coarse[g];
            }
            s_qp = (qp > 0) ? qp - 1 : 0;
        }
        __syncthreads();
        int qp = s_qp;
        for (int i = tid; i < cnt_all; i += NT) {
            ull key = cl[i];
            float s = inv_ordered((unsigned int)(key >> 32));
            if (bin_of(s) >= qp) {
                int pos = atomicAdd(&s_cnt, 1);
                if (pos < CAND) cidx[pos] = (int)(~(unsigned int)key);
                else            s_fallback = 1;
            }
        }
        __syncthreads();
    }

    if (!s_fallback) {
        int m = s_cnt; if (m > CAND) m = CAND;
        for (int it = tid; it < m; it += NT) {
            int idx = cidx[it];
            int HW, W, p, lvl; float stride;
            level_of(idx, HW, W, stride, p, lvl);
            const float* cls = CLS[lvl];
            const float* obj = OBJ[lvl];
            float o  = obj[b * HW + p];
            float c0 = cls[(b * 2 + 0) * HW + p];
            float c1 = cls[(b * 2 + 1) * HW + p];
            float cmax = fmaxf(c0, c1);
            float smax = __fmul_rn(sig_e(o), sig_e(cmax));  // == max(s0,s1)
            ull key = 0ull;
            if (smax > SCORE_THRESH) {
                key = ((ull)ordered_float(smax) << 32) |
                      (unsigned int)(~(unsigned int)idx);
                atomicAdd(&s_nvalid, 1);
                if ((unsigned int)idx < 1024u)
                    atomicOr(&s_vbm[idx >> 5], 1u << (idx & 31));
            }
            ckey[it] = key;
        }
        __syncthreads();

        if (s_nvalid < TOPK) {
            int M = TOPK - s_nvalid;
            if (cnt_all <= CAND && s_cnt + M <= CAND) {
                if (tid == 0) {
                    int acc = 0;
                    for (int w = 0; w < 32; ++w) {
                        s_wpre[w] = acc;
                        acc += 32 - __popc(s_vbm[w]);
                    }
                    s_wpre[32] = acc;
                }
                __syncthreads();
                int base2 = s_cnt;
                {
                    int i = tid;   // NT == 1024 covers [0,1024)
                    unsigned int bmw = s_vbm[i >> 5];
                    bool invalid = !((bmw >> (i & 31)) & 1u);
                    if (invalid) {
                        int rank = s_wpre[i >> 5] +
                                   __popc(~bmw & ((1u << (i & 31)) - 1u));
                        if (rank < M) {
                            ckey[base2 + rank] =
                                ((ull)ordered_float(-1.0f) << 32) |
                                (unsigned int)(~(unsigned int)i);
                        }
                    }
                }
                __syncthreads();
                if (tid == 0) s_cnt = base2 + M;
                __syncthreads();
            } else {
                s_fallback = 1;
            }
        }
    }
    __syncthreads();

    // pathological full-exact fallback (correct, slow, unexpected)
    if (s_fallback) {
        float* sc = g_scores + b * NA;
        for (int i = tid; i < NA; i += NT) {
            int HW, W, p, lvl; float stride;
            level_of(i, HW, W, stride, p, lvl);
            const float* cls = CLS[lvl];
            const float* obj = OBJ[lvl];
            float o  = obj[b * HW + p];
            float c0 = cls[(b * 2 + 0) * HW + p];
            float c1 = cls[(b * 2 + 1) * HW + p];
            float smax = __fmul_rn(sig_e(o), sig_e(fmaxf(c0, c1)));
            sc[i] = (smax > SCORE_THRESH) ? smax : -1.0f;
        }
        if (tid == 0) { s_prefix = 0ull; s_k = TOPK; s_cnt = 0; }
        __syncthreads();
        for (int pp = 7; pp >= 0; --pp) {
            for (int d = tid; d < 256; d += NT) hist[d] = 0;
            __syncthreads();
            ull pref = s_prefix;
            int sh = (pp + 1) * 8;
            for (int i = tid; i < NA; i += NT) {
                ull key = ((ull)ordered_float(sc[i]) << 32) |
                          (unsigned int)(~(unsigned int)i);
                bool match = (pp == 7) || ((key >> sh) == (pref >> sh));
                if (match) atomicAdd(&hist[(unsigned int)(key >> (pp * 8)) & 0xFFu], 1);
            }
            __syncthreads();
            if (tid == 0) {
                int k = s_k;
                for (int d = 255; d >= 0; --d) {
                    int c = hist[d];
                    if (k <= c) { s_prefix = pref | ((ull)d << (pp * 8)); break; }
                    k -= c;
                }
                s_k = k;
            }
            __syncthreads();
        }
        ull pivot = s_prefix;
        for (int i = tid; i < NA; i += NT) {
            ull key = ((ull)ordered_float(sc[i]) << 32) |
                      (unsigned int)(~(unsigned int)i);
            if (key >= pivot) {
                int pos = atomicAdd(&s_cnt, 1);
                if (pos < CAND) ckey[pos] = key;
            }
        }
        __syncthreads();
    }

    // pad + bitonic sort (descending), 1024 elems / 1024 threads
    int cnt = s_cnt; if (cnt > CAND) cnt = CAND;
    if (tid >= cnt) ckey[tid] = 0ull;
    __syncthreads();

    for (int k = 2; k <= CAND; k <<= 1) {
        for (int j = k >> 1; j > 0; j >>= 1) {
            int i = tid;
            int ixj = i ^ j;
            if (ixj > i) {
                bool desc = ((i & k) == 0);
                ull ka = ckey[i], kb = ckey[ixj];
                if (desc ? (ka < kb) : (ka > kb)) { ckey[i] = kb; ckey[ixj] = ka; }
            }
            __syncthreads();
        }
    }

    // ---- transition: grab my key, repurpose shared for NMS ----
    ull myk = ckey[tid];
    __syncthreads();

    // ---- box + label decode for top-500 ----
    int r = tid;
    float4 bb = make_float4(0.f, 0.f, 0.f, 0.f);
    float  sc = -1.0f;
    int    lab = 0;
    bool   validf = false;

    if (r < TOPK) {
        int idx = (int)(~(unsigned int)myk);
        sc = inv_ordered((unsigned int)(myk >> 32));
        if ((unsigned int)idx >= (unsigned int)NA) idx = 0;   // defensive

        int HW, W, p, lvl; float stride;
        level_of(idx, HW, W, stride, p, lvl);
        const float* reg = REG[lvl];
        const float* cls = CLS[lvl];
        const float* obj = OBJ[lvl];
        int y = p / W;
        int x = p - y * W;

        float dx = reg[(b * 4 + 0) * HW + p];
        float dy = reg[(b * 4 + 1) * HW + p];
        float dw = reg[(b * 4 + 2) * HW + p];
        float dh = reg[(b * 4 + 3) * HW + p];
        float cx = __fmul_rn(__fadd_rn((float)x, sig_e(dx)), stride);
        float cy = __fmul_rn(__fadd_rn((float)y, sig_e(dy)), stride);
        float w  = __fmul_rn(exp_cr(dw), stride);
        float h  = __fmul_rn(exp_cr(dh), stride);
        float wh = __fdiv_rn(w, 2.0f);
        float hh = __fdiv_rn(h, 2.0f);
        bb.x = __fsub_rn(cx, wh);
        bb.y = __fsub_rn(cy, hh);
        bb.z = __fadd_rn(cx, wh);
        bb.w = __fadd_rn(cy, hh);

        float c0 = cls[(b * 2 + 0) * HW + p];
        float c1 = cls[(b * 2 + 1) * HW + p];
        if (c1 > c0) {
            if (__fsub_rn(c1, c0) < 1e-3f) {
                float o   = obj[b * HW + p];
                float so2 = sig_e(o);
                float s0  = __fmul_rn(so2, sig_e(c0));
                float s1  = __fmul_rn(so2, sig_e(c1));
                lab = (s1 > s0) ? 1 : 0;
            } else {
                lab = 1;
            }
        }

        float off = __fmul_rn((float)lab, CLASS_OFFSET);
        float x1 = __fadd_rn(bb.x, off);
        float y1 = __fadd_rn(bb.y, off);
        float x2 = __fadd_rn(bb.z, off);
        float y2 = __fadd_rn(bb.w, off);
        sbox[r] = make_float4(x1, y1, x2, y2);
        sar[r]  = __fmul_rn(__fsub_rn(x2, x1), __fsub_rn(y2, y1));
        validf  = (sc > SCORE_THRESH);
    } else if (r < 512) {
        sbox[r] = make_float4(0.f, 0.f, 0.f, 0.f);
        sar[r]  = 0.f;
    }

    unsigned vb = __ballot_sync(0xFFFFFFFFu, validf);
    if (r < 512 && (r & 31) == 0) s_validw[r >> 5] = vb;

    #pragma unroll
    for (int w = 0; w < 8; ++w) adj[tid * 8 + w] = 0u;   // 512*16 words / 1024 thr
    __syncthreads();

    // ---- adjacency: balanced half-pair enumeration, 2 threads per row ----
    {
        int row = tid >> 1;
        int h   = tid & 1;
        float4 mb = sbox[row];
        float  ar = sar[row];
        int kmax = (row < 256) ? 256 : 255;
        int k0 = h ? 129 : 1;
        int k1 = h ? kmax : 128;
        for (int k = k0; k <= k1; ++k) {
            int j = (row + k) & 511;
            float4 bj = sbox[j];
            float  aj = sar[j];
            float ix1 = fmaxf(mb.x, bj.x);
            float iy1 = fmaxf(mb.y, bj.y);
            float ix2 = fminf(mb.z, bj.z);
            float iy2 = fminf(mb.w, bj.w);
            float iw  = fmaxf(__fsub_rn(ix2, ix1), 0.f);
            float ih  = fmaxf(__fsub_rn(iy2, iy1), 0.f);
            float inter = __fmul_rn(iw, ih);
            float uniP  = __fadd_rn(__fsub_rn(__fadd_rn(ar, aj), inter), 1e-7f);
            float t2   = __fmul_rn(0.5f, uniP);
            float diff = __fsub_rn(inter, t2);
            bool hit;
            if (fabsf(diff) <= __fmul_rn(1e-6f, t2)) {
                float iou = __fdiv_rn(inter, uniP);   // exact decision in band
                hit = (iou >= NMS_THRESH);
            } else {
                hit = (diff > 0.f);
            }
            if (hit) {
                atomicOr(&adj[row * 16 + (j >> 5)], 1u << (j & 31));
                atomicOr(&adj[j * 16 + (row >> 5)], 1u << (row & 31));
            }
        }
    }
    __syncthreads();

    // ---- windowed warp greedy (R13): 16 shfls, local window resolution ----
    if (tid < 32) {
        int lane = tid;
        unsigned avail = (lane < 16) ? s_validw[lane] : 0u;
        #pragma unroll 1
        for (int w = 0; w < 16; ++w) {
            unsigned km = 0;
            if (lane == w) {
                unsigned aw = avail;
                unsigned col[32];
                #pragma unroll
                for (int b2 = 0; b2 < 32; ++b2)
                    col[b2] = adj[(w * 32 + b2) * 16 + w];
                #pragma unroll
                for (int b2 = 0; b2 < 32; ++b2) {
                    if ((aw >> b2) & 1u) {
                        km |= 1u << b2;
                        aw &= ~col[b2];
                    }
                }
            }
            km = __shfl_sync(0xFFFFFFFFu, km, w);
            if (lane < 16) {
                #pragma unroll
                for (int b2 = 0; b2 < 32; ++b2) {
                    if ((km >> b2) & 1u)
                        avail &= ~adj[(w * 32 + b2) * 16 + lane];
                }
            }
            if (lane == 0) skeepw[w] = km;
        }
    }
    __syncthreads();

    // ---- outputs: [boxes (B*500*4)] [scores] [labels] [keep] ----
    if (r < TOPK) {
        bool kp = (skeepw[r >> 5] >> (r & 31)) & 1u;
        int row = b * TOPK + r;
        float* ob = out + row * 4;
        ob[0] = kp ? bb.x : 0.f;
        ob[1] = kp ? bb.y : 0.f;
        ob[2] = kp ? bb.z : 0.f;
        ob[3] = kp ? bb.w : 0.f;
        const int SBASE = B * TOPK * 4;
        const int LBASE = SBASE + B * TOPK;
        const int KBASE = LBASE + B * TOPK;
        out[SBASE + row] = kp ? sc : 0.f;
        out[LBASE + row] = (float)lab;
        out[KBASE + row] = kp ? 1.f : 0.f;
    }
}

// --------------------------------------------------------------- launch ----
extern "C" void kernel_launch(void* const* d_in, const int* in_sizes, int n_in,
                              void* d_out, int out_size)
{
    const float* cls_p3 = (const float*)d_in[0];
    const float* reg_p3 = (const float*)d_in[1];
    const float* obj_p3 = (const float*)d_in[2];
    const float* cls_p4 = (const float*)d_in[3];
    const float* reg_p4 = (const float*)d_in[4];
    const float* obj_p4 = (const float*)d_in[5];
    const float* cls_p5 = (const float*)d_in[6];
    const float* reg_p5 = (const float*)d_in[7];
    const float* obj_p5 = (const float*)d_in[8];
    float* out = (float*)d_out;

    void* p_zs = nullptr;
    cudaGetSymbolAddress(&p_zs, g_zs);
    cudaMemsetAsync(p_zs, 0, sizeof(ZeroBlock), 0);   // ONE memset node

    dim3 sgrid(17, B);
    scan_kernel<<<sgrid, 512>>>(cls_p3, obj_p3, cls_p4, obj_p4, cls_p5, obj_p5);
    select_nms_kernel<<<B, 1024>>>(cls_p3, reg_p3, obj_p3,
                                   cls_p4, reg_p4, obj_p4,
                                   cls_p5, reg_p5, obj_p5, out);
}